// round 1
// baseline (speedup 1.0000x reference)
#include <cuda_runtime.h>
#include <math.h>

// ---------------------------------------------------------------------------
// Problem shape (fixed): x[4,256,64,64], cond[4,512]
// ---------------------------------------------------------------------------
#define B_   4
#define C_   256
#define HW_  4096
#define G_   32
#define CPG_ 8               // channels per group
#define CD_  512             // cond dim
#define NTOK (B_*HW_)        // 16384

// ---------------------------------------------------------------------------
// Scratch (device globals — allocation-free rule)
// ---------------------------------------------------------------------------
__device__ float g_sb[B_ * 2 * C_];            // [4,512] scale|bias
__device__ float g_mean[B_ * G_];
__device__ float g_rinv[B_ * G_];
__device__ float g_t[NTOK * C_];               // tokens [B,HW,C]   16.8 MB
__device__ float g_qkv[NTOK * 3 * C_];         // [B,HW,768]        50 MB
__device__ float g_S[(size_t)B_ * HW_ * HW_];  // attn scores       268 MB
__device__ float g_o[NTOK * C_];               // attn out
__device__ float g_o2[NTOK * C_];              // proj out

// ---------------------------------------------------------------------------
// 1) cond @ lin_w + lin_b  ->  g_sb [B, 512]
// ---------------------------------------------------------------------------
__global__ void cond_linear_kernel(const float* __restrict__ cond,
                                   const float* __restrict__ w,
                                   const float* __restrict__ bias,
                                   float* __restrict__ sb) {
    __shared__ float cs[CD_];
    int b = blockIdx.y;
    for (int k = threadIdx.x; k < CD_; k += 256) cs[k] = cond[b * CD_ + k];
    __syncthreads();
    int j = blockIdx.x * 256 + threadIdx.x;     // 0..511
    float acc = bias[j];
    #pragma unroll 8
    for (int k = 0; k < CD_; k++) acc += cs[k] * w[k * (2 * C_) + j];
    sb[b * (2 * C_) + j] = acc;
}

// ---------------------------------------------------------------------------
// 2) GroupNorm stats: one block per (b,g); 8*4096 = 32768 contiguous floats
// ---------------------------------------------------------------------------
__global__ void gn_stats_kernel(const float* __restrict__ x,
                                float* __restrict__ mean,
                                float* __restrict__ rinv) {
    const int bg = blockIdx.x;                   // 0..127
    const float* p = x + (size_t)bg * CPG_ * HW_;
    float s = 0.f, ss = 0.f;
    for (int i = threadIdx.x; i < CPG_ * HW_; i += 256) {
        float v = p[i];
        s += v; ss += v * v;
    }
    __shared__ float sm_s[8], sm_ss[8];
    #pragma unroll
    for (int o = 16; o > 0; o >>= 1) {
        s  += __shfl_xor_sync(0xffffffffu, s,  o);
        ss += __shfl_xor_sync(0xffffffffu, ss, o);
    }
    if ((threadIdx.x & 31) == 0) { sm_s[threadIdx.x >> 5] = s; sm_ss[threadIdx.x >> 5] = ss; }
    __syncthreads();
    if (threadIdx.x == 0) {
        s = 0.f; ss = 0.f;
        #pragma unroll
        for (int i = 0; i < 8; i++) { s += sm_s[i]; ss += sm_ss[i]; }
        float m = s * (1.f / (CPG_ * HW_));
        float var = ss * (1.f / (CPG_ * HW_)) - m * m;
        mean[bg] = m;
        rinv[bg] = rsqrtf(var + 1e-5f);
    }
}

// ---------------------------------------------------------------------------
// 3) GN apply + affine, transposed write -> g_t [B, HW, C]
//    grid (HW/32, C/32, B), block (32, 8)
// ---------------------------------------------------------------------------
__global__ void gn_apply_t_kernel(const float* __restrict__ x,
                                  const float* __restrict__ sb,
                                  const float* __restrict__ mean,
                                  const float* __restrict__ rinv,
                                  float* __restrict__ t) {
    __shared__ float tile[32][33];
    const int b = blockIdx.z;
    const int c0 = blockIdx.y * 32, n0 = blockIdx.x * 32;
    #pragma unroll
    for (int i = threadIdx.y; i < 32; i += 8) {
        int c = c0 + i;
        int g = b * G_ + (c >> 3);
        float m = mean[g], r = rinv[g];
        float sc = 1.f + sb[b * 2 * C_ + c];
        float bi = sb[b * 2 * C_ + C_ + c];
        float v = x[((size_t)b * C_ + c) * HW_ + n0 + threadIdx.x];
        tile[i][threadIdx.x] = (v - m) * r * sc + bi;
    }
    __syncthreads();
    #pragma unroll
    for (int i = threadIdx.y; i < 32; i += 8) {
        int n = n0 + i;
        t[((size_t)b * HW_ + n) * C_ + c0 + threadIdx.x] = tile[threadIdx.x][i];
    }
}

// ---------------------------------------------------------------------------
// Generic 64x64x16 register-blocked fp32 GEMM.  C = alpha * A*B (+bias)
//   A: [M,K] row-major (lda).  B: NN -> [K,N] (ldb);  NT -> [N,K] (ldb)
//   256 threads, 4x4 microtile.  All dims divide tile sizes exactly.
// ---------------------------------------------------------------------------
template <bool TRANSB, bool HASBIAS>
__global__ void gemm64_kernel(const float* __restrict__ A, int lda, size_t strideA,
                              const float* __restrict__ Bm, int ldb, size_t strideB,
                              float* __restrict__ Cm, int ldc, size_t strideC,
                              int K, float alpha, const float* __restrict__ bias) {
    constexpr int BM = 64, BN = 64, BK = 16;
    const int bz = blockIdx.z;
    A  += (size_t)bz * strideA;
    Bm += (size_t)bz * strideB;
    Cm += (size_t)bz * strideC;

    __shared__ float As[BK][BM + 1];
    __shared__ float Bs[BK][BN + 1];

    const int tid = threadIdx.x;
    const int tx = tid & 15, ty = tid >> 4;
    const int m0 = blockIdx.y * BM, n0 = blockIdx.x * BN;

    float acc[4][4] = {};

    for (int k0 = 0; k0 < K; k0 += BK) {
        {   // load A tile: 64 rows x 16 k, 4 consecutive k per thread
            int m  = tid >> 2;
            int kq = (tid & 3) * 4;
            const float* ap = A + (size_t)(m0 + m) * lda + k0 + kq;
            #pragma unroll
            for (int j = 0; j < 4; j++) As[kq + j][m] = ap[j];
        }
        if (TRANSB) {   // B is [N,K]: read 4 consecutive k per thread
            int n  = tid >> 2;
            int kq = (tid & 3) * 4;
            const float* bp = Bm + (size_t)(n0 + n) * ldb + k0 + kq;
            #pragma unroll
            for (int j = 0; j < 4; j++) Bs[kq + j][n] = bp[j];
        } else {        // B is [K,N]: read 4 consecutive n per thread
            int k  = tid >> 4;
            int nq = (tid & 15) * 4;
            const float* bp = Bm + (size_t)(k0 + k) * ldb + n0 + nq;
            #pragma unroll
            for (int j = 0; j < 4; j++) Bs[k][nq + j] = bp[j];
        }
        __syncthreads();
        #pragma unroll
        for (int k = 0; k < BK; k++) {
            float a[4], bf[4];
            #pragma unroll
            for (int i = 0; i < 4; i++) a[i]  = As[k][ty * 4 + i];
            #pragma unroll
            for (int j = 0; j < 4; j++) bf[j] = Bs[k][tx * 4 + j];
            #pragma unroll
            for (int i = 0; i < 4; i++)
                #pragma unroll
                for (int j = 0; j < 4; j++) acc[i][j] += a[i] * bf[j];
        }
        __syncthreads();
    }

    #pragma unroll
    for (int i = 0; i < 4; i++) {
        int m = m0 + ty * 4 + i;
        float* cp = Cm + (size_t)m * ldc + n0 + tx * 4;
        #pragma unroll
        for (int j = 0; j < 4; j++) {
            float v = acc[i][j] * alpha;
            if (HASBIAS) v += bias[n0 + tx * 4 + j];
            cp[j] = v;
        }
    }
}

// ---------------------------------------------------------------------------
// 6) Row softmax over S rows of length 4096 (one block / row, 256 threads)
// ---------------------------------------------------------------------------
__global__ void softmax_rows_kernel(float* __restrict__ S) {
    const size_t row = blockIdx.x;
    float* p = S + row * (size_t)HW_;
    const int tid = threadIdx.x;
    float v[16];
    float mx = -1e30f;
    #pragma unroll
    for (int i = 0; i < 16; i++) { v[i] = p[tid + i * 256]; mx = fmaxf(mx, v[i]); }

    __shared__ float sm[8];
    #pragma unroll
    for (int o = 16; o > 0; o >>= 1) mx = fmaxf(mx, __shfl_xor_sync(0xffffffffu, mx, o));
    if ((tid & 31) == 0) sm[tid >> 5] = mx;
    __syncthreads();
    mx = sm[0];
    #pragma unroll
    for (int i = 1; i < 8; i++) mx = fmaxf(mx, sm[i]);

    float s = 0.f;
    #pragma unroll
    for (int i = 0; i < 16; i++) { v[i] = __expf(v[i] - mx); s += v[i]; }
    __shared__ float sm2[8];
    #pragma unroll
    for (int o = 16; o > 0; o >>= 1) s += __shfl_xor_sync(0xffffffffu, s, o);
    if ((tid & 31) == 0) sm2[tid >> 5] = s;
    __syncthreads();
    s = 0.f;
    #pragma unroll
    for (int i = 0; i < 8; i++) s += sm2[i];
    float inv = 1.f / s;
    #pragma unroll
    for (int i = 0; i < 16; i++) p[tid + i * 256] = v[i] * inv;
}

// ---------------------------------------------------------------------------
// 9) out[b,c,n] = x[b,c,n] + o2[b,n,c]   (transpose tile)
//    grid (HW/32, C/32, B), block (32, 8)
// ---------------------------------------------------------------------------
__global__ void residual_t_kernel(const float* __restrict__ o2,
                                  const float* __restrict__ x,
                                  float* __restrict__ out) {
    __shared__ float tile[32][33];
    const int b = blockIdx.z;
    const int n0 = blockIdx.x * 32, c0 = blockIdx.y * 32;
    #pragma unroll
    for (int i = threadIdx.y; i < 32; i += 8) {
        int n = n0 + i;
        tile[i][threadIdx.x] = o2[((size_t)b * HW_ + n) * C_ + c0 + threadIdx.x];
    }
    __syncthreads();
    #pragma unroll
    for (int i = threadIdx.y; i < 32; i += 8) {
        int c = c0 + i;
        size_t idx = ((size_t)b * C_ + c) * HW_ + n0 + threadIdx.x;
        out[idx] = x[idx] + tile[threadIdx.x][i];
    }
}

// ---------------------------------------------------------------------------
// Host launcher
// ---------------------------------------------------------------------------
extern "C" void kernel_launch(void* const* d_in, const int* in_sizes, int n_in,
                              void* d_out, int out_size) {
    const float* x      = (const float*)d_in[0];
    const float* cond   = (const float*)d_in[1];
    const float* lin_w  = (const float*)d_in[2];
    const float* lin_b  = (const float*)d_in[3];
    const float* qkv_w  = (const float*)d_in[4];
    const float* qkv_b  = (const float*)d_in[5];
    const float* proj_w = (const float*)d_in[6];
    const float* proj_b = (const float*)d_in[7];
    float* out = (float*)d_out;

    float *sb, *mean, *rinv, *t, *qkv, *S, *o, *o2;
    cudaGetSymbolAddress((void**)&sb,   g_sb);
    cudaGetSymbolAddress((void**)&mean, g_mean);
    cudaGetSymbolAddress((void**)&rinv, g_rinv);
    cudaGetSymbolAddress((void**)&t,    g_t);
    cudaGetSymbolAddress((void**)&qkv,  g_qkv);
    cudaGetSymbolAddress((void**)&S,    g_S);
    cudaGetSymbolAddress((void**)&o,    g_o);
    cudaGetSymbolAddress((void**)&o2,   g_o2);

    // 1) scale/bias from cond
    cond_linear_kernel<<<dim3(2, B_), 256>>>(cond, lin_w, lin_b, sb);

    // 2) groupnorm stats
    gn_stats_kernel<<<B_ * G_, 256>>>(x, mean, rinv);

    // 3) apply + transpose -> tokens
    gn_apply_t_kernel<<<dim3(HW_ / 32, C_ / 32, B_), dim3(32, 8)>>>(x, sb, mean, rinv, t);

    // 4) qkv = t @ qkv_w + qkv_b      [16384, 768]
    gemm64_kernel<false, true><<<dim3(3 * C_ / 64, NTOK / 64, 1), 256>>>(
        t, C_, 0, qkv_w, 3 * C_, 0, qkv, 3 * C_, 0, C_, 1.0f, qkv_b);

    // 5) S = Q @ K^T / 16             batched over B
    gemm64_kernel<true, false><<<dim3(HW_ / 64, HW_ / 64, B_), 256>>>(
        qkv, 3 * C_, (size_t)HW_ * 3 * C_,            // Q  (cols 0..255)
        qkv + C_, 3 * C_, (size_t)HW_ * 3 * C_,       // K  (cols 256..511)
        S, HW_, (size_t)HW_ * HW_,
        C_, 0.0625f, nullptr);

    // 6) softmax rows
    softmax_rows_kernel<<<NTOK, 256>>>(S);

    // 7) O = P @ V                    batched over B
    gemm64_kernel<false, false><<<dim3(C_ / 64, HW_ / 64, B_), 256>>>(
        S, HW_, (size_t)HW_ * HW_,
        qkv + 2 * C_, 3 * C_, (size_t)HW_ * 3 * C_,   // V  (cols 512..767)
        o, C_, (size_t)HW_ * C_,
        HW_, 1.0f, nullptr);

    // 8) proj
    gemm64_kernel<false, true><<<dim3(C_ / 64, NTOK / 64, 1), 256>>>(
        o, C_, 0, proj_w, C_, 0, o2, C_, 0, C_, 1.0f, proj_b);

    // 9) residual + transpose back to [B,C,H,W]
    residual_t_kernel<<<dim3(HW_ / 32, C_ / 32, B_), dim3(32, 8)>>>(o2, x, out);
}

// round 3
// speedup vs baseline: 6.0382x; 6.0382x over previous
#include <cuda_runtime.h>
#include <cuda_bf16.h>
#include <stdint.h>
#include <math.h>

// ---------------------------------------------------------------------------
// Problem shape (fixed): x[4,256,64,64], cond[4,512]
// ---------------------------------------------------------------------------
#define B_   4
#define C_   256
#define HW_  4096
#define G_   32
#define CPG_ 8
#define CD_  512
#define NTOK (B_*HW_)        // 16384

// ---------------------------------------------------------------------------
// Scratch (device globals)
// ---------------------------------------------------------------------------
__device__ float g_sb[B_ * 2 * C_];
__device__ float g_mean[B_ * G_];
__device__ float g_rinv[B_ * G_];
__device__ __nv_bfloat16 g_t[NTOK * C_];                 // tokens bf16
__device__ __nv_bfloat16 g_qkv[NTOK * 3 * C_];           // qkv bf16
__device__ __nv_bfloat16 g_S[(size_t)B_ * HW_ * HW_];    // scores/probs bf16 (134MB)
__device__ __nv_bfloat16 g_vt[(size_t)B_ * C_ * HW_];    // V^T bf16
__device__ __nv_bfloat16 g_o[NTOK * C_];
__device__ __nv_bfloat16 g_o2[NTOK * C_];
__device__ __nv_bfloat16 g_wq[3 * C_ * C_];              // qkv_w^T bf16 [768,256]
__device__ __nv_bfloat16 g_wp[C_ * C_];                  // proj_w^T bf16 [256,256]

// ---------------------------------------------------------------------------
// 1) cond @ lin_w + lin_b  ->  g_sb [B, 512]
// ---------------------------------------------------------------------------
__global__ void cond_linear_kernel(const float* __restrict__ cond,
                                   const float* __restrict__ w,
                                   const float* __restrict__ bias,
                                   float* __restrict__ sb) {
    __shared__ float cs[CD_];
    int b = blockIdx.y;
    for (int k = threadIdx.x; k < CD_; k += 256) cs[k] = cond[b * CD_ + k];
    __syncthreads();
    int j = blockIdx.x * 256 + threadIdx.x;
    float acc = bias[j];
    #pragma unroll 8
    for (int k = 0; k < CD_; k++) acc += cs[k] * w[k * (2 * C_) + j];
    sb[b * (2 * C_) + j] = acc;
}

// ---------------------------------------------------------------------------
// 2) GroupNorm stats
// ---------------------------------------------------------------------------
__global__ void gn_stats_kernel(const float* __restrict__ x,
                                float* __restrict__ mean,
                                float* __restrict__ rinv) {
    const int bg = blockIdx.x;
    const float* p = x + (size_t)bg * CPG_ * HW_;
    float s = 0.f, ss = 0.f;
    for (int i = threadIdx.x; i < CPG_ * HW_; i += 256) {
        float v = p[i];
        s += v; ss += v * v;
    }
    __shared__ float sm_s[8], sm_ss[8];
    #pragma unroll
    for (int o = 16; o > 0; o >>= 1) {
        s  += __shfl_xor_sync(0xffffffffu, s,  o);
        ss += __shfl_xor_sync(0xffffffffu, ss, o);
    }
    if ((threadIdx.x & 31) == 0) { sm_s[threadIdx.x >> 5] = s; sm_ss[threadIdx.x >> 5] = ss; }
    __syncthreads();
    if (threadIdx.x == 0) {
        s = 0.f; ss = 0.f;
        #pragma unroll
        for (int i = 0; i < 8; i++) { s += sm_s[i]; ss += sm_ss[i]; }
        float m = s * (1.f / (CPG_ * HW_));
        float var = ss * (1.f / (CPG_ * HW_)) - m * m;
        mean[bg] = m;
        rinv[bg] = rsqrtf(var + 1e-5f);
    }
}

// ---------------------------------------------------------------------------
// 3) GN apply + affine, transpose -> g_t bf16 [B, HW, C]
// ---------------------------------------------------------------------------
__global__ void gn_apply_t_kernel(const float* __restrict__ x,
                                  const float* __restrict__ sb,
                                  const float* __restrict__ mean,
                                  const float* __restrict__ rinv,
                                  __nv_bfloat16* __restrict__ t) {
    __shared__ float tile[32][33];
    const int b = blockIdx.z;
    const int c0 = blockIdx.y * 32, n0 = blockIdx.x * 32;
    #pragma unroll
    for (int i = threadIdx.y; i < 32; i += 8) {
        int c = c0 + i;
        int g = b * G_ + (c >> 3);
        float m = mean[g], r = rinv[g];
        float sc = 1.f + sb[b * 2 * C_ + c];
        float bi = sb[b * 2 * C_ + C_ + c];
        float v = x[((size_t)b * C_ + c) * HW_ + n0 + threadIdx.x];
        tile[i][threadIdx.x] = (v - m) * r * sc + bi;
    }
    __syncthreads();
    #pragma unroll
    for (int i = threadIdx.y; i < 32; i += 8) {
        int n = n0 + i;
        t[((size_t)b * HW_ + n) * C_ + c0 + threadIdx.x] =
            __float2bfloat16(tile[threadIdx.x][i]);
    }
}

// ---------------------------------------------------------------------------
// Weight transpose + convert: w fp32 [256, N] -> wt bf16 [N, 256]
// ---------------------------------------------------------------------------
__global__ void wt_kernel(const float* __restrict__ w,
                          __nv_bfloat16* __restrict__ wt, int N) {
    __shared__ float tile[32][33];
    const int k0 = blockIdx.y * 32, n0 = blockIdx.x * 32;
    #pragma unroll
    for (int i = threadIdx.y; i < 32; i += 8)
        tile[i][threadIdx.x] = w[(size_t)(k0 + i) * N + n0 + threadIdx.x];
    __syncthreads();
    #pragma unroll
    for (int i = threadIdx.y; i < 32; i += 8)
        wt[(size_t)(n0 + i) * C_ + k0 + threadIdx.x] =
            __float2bfloat16(tile[threadIdx.x][i]);
}

// ---------------------------------------------------------------------------
// V^T: qkv[b, n, 512+c] -> vt[b, c, n]
// ---------------------------------------------------------------------------
__global__ void vt_kernel(const __nv_bfloat16* __restrict__ qkv,
                          __nv_bfloat16* __restrict__ vt) {
    __shared__ __nv_bfloat16 tile[32][33];
    const int b = blockIdx.z;
    const int n0 = blockIdx.x * 32, c0 = blockIdx.y * 32;
    #pragma unroll
    for (int i = threadIdx.y; i < 32; i += 8)
        tile[i][threadIdx.x] =
            qkv[((size_t)b * HW_ + n0 + i) * (3 * C_) + 2 * C_ + c0 + threadIdx.x];
    __syncthreads();
    #pragma unroll
    for (int i = threadIdx.y; i < 32; i += 8)
        vt[((size_t)b * C_ + c0 + i) * HW_ + n0 + threadIdx.x] = tile[threadIdx.x][i];
}

// ---------------------------------------------------------------------------
// bf16 NT GEMM: C[M,N] = alpha * A[M,K] @ B[N,K]^T (+ bias), out bf16
//   128x128x64 block tile, 8 warps (4x2), warp tile 32x64, mma m16n8k16
// ---------------------------------------------------------------------------
#define BKg 64
#define PADg 8
#define LDKg (BKg + PADg)   // 72 halves -> conflict-free fragment loads

__device__ __forceinline__ void mma_bf16(float c[4],
                                         uint32_t a0, uint32_t a1, uint32_t a2, uint32_t a3,
                                         uint32_t b0, uint32_t b1) {
    asm volatile(
        "mma.sync.aligned.m16n8k16.row.col.f32.bf16.bf16.f32 "
        "{%0,%1,%2,%3},{%4,%5,%6,%7},{%8,%9},{%0,%1,%2,%3};\n"
        : "+f"(c[0]), "+f"(c[1]), "+f"(c[2]), "+f"(c[3])
        : "r"(a0), "r"(a1), "r"(a2), "r"(a3), "r"(b0), "r"(b1));
}

template <bool HASBIAS>
__global__ void gemm_nt_bf16(const __nv_bfloat16* __restrict__ A, int lda, size_t sA,
                             const __nv_bfloat16* __restrict__ Bm, int ldb, size_t sB,
                             __nv_bfloat16* __restrict__ Cm, int ldc, size_t sC,
                             int K, float alpha, const float* __restrict__ bias) {
    __shared__ __nv_bfloat16 As[128 * LDKg];
    __shared__ __nv_bfloat16 Bs[128 * LDKg];

    const int bz = blockIdx.z;
    A  += (size_t)bz * sA;
    Bm += (size_t)bz * sB;
    Cm += (size_t)bz * sC;

    const int m0 = blockIdx.y * 128, n0 = blockIdx.x * 128;
    const int tid = threadIdx.x;
    const int lane = tid & 31, warp = tid >> 5;
    const int wm = (warp & 3) * 32;
    const int wn = (warp >> 2) * 64;

    const int lr = tid >> 1;
    const int lc = (tid & 1) * 32;
    const __nv_bfloat16* aptr = A  + (size_t)(m0 + lr) * lda + lc;
    const __nv_bfloat16* bptr = Bm + (size_t)(n0 + lr) * ldb + lc;

    float acc[2][8][4] = {};
    uint4 ra[4], rb[4];

    #pragma unroll
    for (int j = 0; j < 4; j++) {
        ra[j] = *(const uint4*)(aptr + j * 8);
        rb[j] = *(const uint4*)(bptr + j * 8);
    }
    #pragma unroll
    for (int j = 0; j < 4; j++) {
        *(uint4*)&As[lr * LDKg + lc + j * 8] = ra[j];
        *(uint4*)&Bs[lr * LDKg + lc + j * 8] = rb[j];
    }
    __syncthreads();

    const int fr = lane >> 2;            // fragment row within 8
    const int fc = (lane & 3) * 2;       // fragment k pair

    for (int k0 = 0; k0 < K; k0 += BKg) {
        const bool more = (k0 + BKg) < K;
        if (more) {
            #pragma unroll
            for (int j = 0; j < 4; j++) {
                ra[j] = *(const uint4*)(aptr + k0 + BKg + j * 8);
                rb[j] = *(const uint4*)(bptr + k0 + BKg + j * 8);
            }
        }
        #pragma unroll
        for (int ks = 0; ks < BKg; ks += 16) {
            uint32_t af[2][4], bfr[8][2];
            #pragma unroll
            for (int mt = 0; mt < 2; mt++) {
                const __nv_bfloat16* base = &As[(wm + mt * 16 + fr) * LDKg + ks + fc];
                af[mt][0] = *(const uint32_t*)(base);
                af[mt][1] = *(const uint32_t*)(base + 8 * LDKg);
                af[mt][2] = *(const uint32_t*)(base + 8);
                af[mt][3] = *(const uint32_t*)(base + 8 * LDKg + 8);
            }
            #pragma unroll
            for (int nt = 0; nt < 8; nt++) {
                const __nv_bfloat16* base = &Bs[(wn + nt * 8 + fr) * LDKg + ks + fc];
                bfr[nt][0] = *(const uint32_t*)(base);
                bfr[nt][1] = *(const uint32_t*)(base + 8);
            }
            #pragma unroll
            for (int mt = 0; mt < 2; mt++)
                #pragma unroll
                for (int nt = 0; nt < 8; nt++)
                    mma_bf16(acc[mt][nt], af[mt][0], af[mt][1], af[mt][2], af[mt][3],
                             bfr[nt][0], bfr[nt][1]);
        }
        __syncthreads();
        if (more) {
            #pragma unroll
            for (int j = 0; j < 4; j++) {
                *(uint4*)&As[lr * LDKg + lc + j * 8] = ra[j];
                *(uint4*)&Bs[lr * LDKg + lc + j * 8] = rb[j];
            }
            __syncthreads();
        }
    }

    // epilogue
    #pragma unroll
    for (int mt = 0; mt < 2; mt++) {
        #pragma unroll
        for (int nt = 0; nt < 8; nt++) {
            int gn = n0 + wn + nt * 8 + fc;
            float b0 = 0.f, b1 = 0.f;
            if (HASBIAS) { b0 = bias[gn]; b1 = bias[gn + 1]; }
            #pragma unroll
            for (int rr = 0; rr < 2; rr++) {
                int gm = m0 + wm + mt * 16 + fr + rr * 8;
                float v0 = acc[mt][nt][rr * 2 + 0] * alpha + b0;
                float v1 = acc[mt][nt][rr * 2 + 1] * alpha + b1;
                __nv_bfloat162 pk = __floats2bfloat162_rn(v0, v1);
                *(__nv_bfloat162*)&Cm[(size_t)gm * ldc + gn] = pk;
            }
        }
    }
}

// ---------------------------------------------------------------------------
// Row softmax, bf16 in/out, fp32 math; one block per row (4096 elements)
// ---------------------------------------------------------------------------
__global__ void softmax_rows_bf16(__nv_bfloat16* __restrict__ S) {
    const size_t row = blockIdx.x;
    __nv_bfloat162* p = (__nv_bfloat162*)(S + row * (size_t)HW_);
    const int tid = threadIdx.x;

    float v[16];
    float mx = -1e30f;
    #pragma unroll
    for (int i = 0; i < 8; i++) {
        __nv_bfloat162 x2 = p[tid + i * 256];
        v[2 * i]     = __bfloat162float(x2.x);
        v[2 * i + 1] = __bfloat162float(x2.y);
        mx = fmaxf(mx, fmaxf(v[2 * i], v[2 * i + 1]));
    }
    __shared__ float sm[8];
    #pragma unroll
    for (int o = 16; o > 0; o >>= 1) mx = fmaxf(mx, __shfl_xor_sync(0xffffffffu, mx, o));
    if ((tid & 31) == 0) sm[tid >> 5] = mx;
    __syncthreads();
    mx = sm[0];
    #pragma unroll
    for (int i = 1; i < 8; i++) mx = fmaxf(mx, sm[i]);

    float s = 0.f;
    #pragma unroll
    for (int i = 0; i < 16; i++) { v[i] = __expf(v[i] - mx); s += v[i]; }
    __shared__ float sm2[8];
    #pragma unroll
    for (int o = 16; o > 0; o >>= 1) s += __shfl_xor_sync(0xffffffffu, s, o);
    if ((tid & 31) == 0) sm2[tid >> 5] = s;
    __syncthreads();
    s = 0.f;
    #pragma unroll
    for (int i = 0; i < 8; i++) s += sm2[i];
    const float inv = 1.f / s;
    #pragma unroll
    for (int i = 0; i < 8; i++)
        p[tid + i * 256] = __floats2bfloat162_rn(v[2 * i] * inv, v[2 * i + 1] * inv);
}

// ---------------------------------------------------------------------------
// Residual: out[b,c,n] = x[b,c,n] + o2[b,n,c]
// ---------------------------------------------------------------------------
__global__ void residual_t_kernel(const __nv_bfloat16* __restrict__ o2,
                                  const float* __restrict__ x,
                                  float* __restrict__ out) {
    __shared__ float tile[32][33];
    const int b = blockIdx.z;
    const int n0 = blockIdx.x * 32, c0 = blockIdx.y * 32;
    #pragma unroll
    for (int i = threadIdx.y; i < 32; i += 8) {
        int n = n0 + i;
        tile[i][threadIdx.x] =
            __bfloat162float(o2[((size_t)b * HW_ + n) * C_ + c0 + threadIdx.x]);
    }
    __syncthreads();
    #pragma unroll
    for (int i = threadIdx.y; i < 32; i += 8) {
        int c = c0 + i;
        size_t idx = ((size_t)b * C_ + c) * HW_ + n0 + threadIdx.x;
        out[idx] = x[idx] + tile[threadIdx.x][i];
    }
}

// ---------------------------------------------------------------------------
// Host launcher
// ---------------------------------------------------------------------------
extern "C" void kernel_launch(void* const* d_in, const int* in_sizes, int n_in,
                              void* d_out, int out_size) {
    const float* x      = (const float*)d_in[0];
    const float* cond   = (const float*)d_in[1];
    const float* lin_w  = (const float*)d_in[2];
    const float* lin_b  = (const float*)d_in[3];
    const float* qkv_w  = (const float*)d_in[4];
    const float* qkv_b  = (const float*)d_in[5];
    const float* proj_w = (const float*)d_in[6];
    const float* proj_b = (const float*)d_in[7];
    float* out = (float*)d_out;

    float *sb, *mean, *rinv;
    __nv_bfloat16 *t, *qkv, *S, *vt, *o, *o2, *wq, *wp;
    cudaGetSymbolAddress((void**)&sb,   g_sb);
    cudaGetSymbolAddress((void**)&mean, g_mean);
    cudaGetSymbolAddress((void**)&rinv, g_rinv);
    cudaGetSymbolAddress((void**)&t,    g_t);
    cudaGetSymbolAddress((void**)&qkv,  g_qkv);
    cudaGetSymbolAddress((void**)&S,    g_S);
    cudaGetSymbolAddress((void**)&vt,   g_vt);
    cudaGetSymbolAddress((void**)&o,    g_o);
    cudaGetSymbolAddress((void**)&o2,   g_o2);
    cudaGetSymbolAddress((void**)&wq,   g_wq);
    cudaGetSymbolAddress((void**)&wp,   g_wp);

    // prep: scale/bias, GN stats, weight transposes (independent)
    cond_linear_kernel<<<dim3(2, B_), 256>>>(cond, lin_w, lin_b, sb);
    gn_stats_kernel<<<B_ * G_, 256>>>(x, mean, rinv);
    wt_kernel<<<dim3(3 * C_ / 32, C_ / 32), dim3(32, 8)>>>(qkv_w, wq, 3 * C_);
    wt_kernel<<<dim3(C_ / 32, C_ / 32), dim3(32, 8)>>>(proj_w, wp, C_);

    // GN apply + transpose -> tokens (bf16)
    gn_apply_t_kernel<<<dim3(HW_ / 32, C_ / 32, B_), dim3(32, 8)>>>(x, sb, mean, rinv, t);

    // qkv = t @ qkv_w + b    [16384, 768]
    gemm_nt_bf16<true><<<dim3(3 * C_ / 128, NTOK / 128, 1), 256>>>(
        t, C_, 0, wq, C_, 0, qkv, 3 * C_, 0, C_, 1.0f, qkv_b);

    // S = Q @ K^T / 16       batched
    gemm_nt_bf16<false><<<dim3(HW_ / 128, HW_ / 128, B_), 256>>>(
        qkv, 3 * C_, (size_t)HW_ * 3 * C_,
        qkv + C_, 3 * C_, (size_t)HW_ * 3 * C_,
        S, HW_, (size_t)HW_ * HW_,
        C_, 0.0625f, nullptr);

    // softmax rows (in place, bf16)
    softmax_rows_bf16<<<NTOK, 256>>>(S);

    // V^T
    vt_kernel<<<dim3(HW_ / 32, C_ / 32, B_), dim3(32, 8)>>>(qkv, vt);

    // O = P @ V              batched  (B operand = V^T, NT form)
    gemm_nt_bf16<false><<<dim3(C_ / 128, HW_ / 128, B_), 256>>>(
        S, HW_, (size_t)HW_ * HW_,
        vt, HW_, (size_t)C_ * HW_,
        o, C_, (size_t)HW_ * C_,
        HW_, 1.0f, nullptr);

    // proj
    gemm_nt_bf16<true><<<dim3(C_ / 128, NTOK / 128, 1), 256>>>(
        o, C_, 0, wp, C_, 0, o2, C_, 0, C_, 1.0f, proj_b);

    // residual + transpose back
    residual_t_kernel<<<dim3(HW_ / 32, C_ / 32, B_), dim3(32, 8)>>>(o2, x, out);
}

// round 5
// speedup vs baseline: 6.5075x; 1.0777x over previous
#include <cuda_runtime.h>
#include <cuda_bf16.h>
#include <stdint.h>
#include <math.h>

#define B_   4
#define C_   256
#define HW_  4096
#define G_   32
#define CPG_ 8
#define CD_  512
#define NTOK (B_*HW_)

// ---------------------------------------------------------------------------
// Scratch (device globals)
// ---------------------------------------------------------------------------
__device__ float g_sb[B_ * 2 * C_];
__device__ float g_mean[B_ * G_];
__device__ float g_rinv[B_ * G_];
__device__ __nv_bfloat16 g_t[NTOK * C_];
__device__ __nv_bfloat16 g_qkv[NTOK * 3 * C_];
__device__ __nv_bfloat16 g_S[(size_t)B_ * HW_ * HW_];
__device__ __nv_bfloat16 g_vt[(size_t)B_ * C_ * HW_];
__device__ __nv_bfloat16 g_o[NTOK * C_];
__device__ __nv_bfloat16 g_o2[NTOK * C_];
__device__ __nv_bfloat16 g_wq[3 * C_ * C_];
__device__ __nv_bfloat16 g_wp[C_ * C_];

// ---------------------------------------------------------------------------
// PTX helpers
// ---------------------------------------------------------------------------
__device__ __forceinline__ uint32_t smem_u32(const void* p) {
    uint32_t a;
    asm("{ .reg .u64 t; cvta.to.shared.u64 t, %1; cvt.u32.u64 %0, t; }" : "=r"(a) : "l"(p));
    return a;
}
__device__ __forceinline__ void cp16(uint32_t dst, const void* src) {
    asm volatile("cp.async.cg.shared.global [%0], [%1], 16;" :: "r"(dst), "l"(src));
}
#define CP_COMMIT() asm volatile("cp.async.commit_group;" ::: "memory")
#define CP_WAIT(n)  asm volatile("cp.async.wait_group %0;" :: "n"(n) : "memory")

__device__ __forceinline__ void ldsm4(uint32_t& r0, uint32_t& r1, uint32_t& r2, uint32_t& r3,
                                      uint32_t addr) {
    asm volatile("ldmatrix.sync.aligned.m8n8.x4.shared.b16 {%0,%1,%2,%3}, [%4];"
                 : "=r"(r0), "=r"(r1), "=r"(r2), "=r"(r3) : "r"(addr));
}
__device__ __forceinline__ void mma_bf16(float c[4],
                                         uint32_t a0, uint32_t a1, uint32_t a2, uint32_t a3,
                                         uint32_t b0, uint32_t b1) {
    asm volatile(
        "mma.sync.aligned.m16n8k16.row.col.f32.bf16.bf16.f32 "
        "{%0,%1,%2,%3},{%4,%5,%6,%7},{%8,%9},{%0,%1,%2,%3};\n"
        : "+f"(c[0]), "+f"(c[1]), "+f"(c[2]), "+f"(c[3])
        : "r"(a0), "r"(a1), "r"(a2), "r"(a3), "r"(b0), "r"(b1));
}

// ---------------------------------------------------------------------------
// bf16 NT GEMM: C[M,N] = alpha*A[M,K]@B[N,K]^T (+bias)
//   BM=BN=128, BK=64; cp.async 2-stage; ldmatrix fragments; 8 warps (4m x 2n)
//   smem rows padded to 72 halves (144B) -> conflict-free ldmatrix
// ---------------------------------------------------------------------------
#define LDK 72
#define ASZ (128 * LDK * 2)     // 18432 B per operand per stage
#define STG (2 * ASZ)           // 36864 B per stage (A + B)
#define GSM (2 * STG)           // 73728 B total

template <bool HASBIAS>
__global__ void __launch_bounds__(256)
gemm_nt_bf16(const __nv_bfloat16* __restrict__ A, int lda, size_t sA,
             const __nv_bfloat16* __restrict__ Bm, int ldb, size_t sB,
             __nv_bfloat16* __restrict__ Cm, int ldc, size_t sC,
             int K, float alpha, const float* __restrict__ bias) {
    extern __shared__ char smraw[];
    const uint32_t sb = smem_u32(smraw);

    const int bz = blockIdx.z;
    A  += (size_t)bz * sA;
    Bm += (size_t)bz * sB;
    Cm += (size_t)bz * sC;

    const int m0 = blockIdx.y * 128, n0 = blockIdx.x * 128;
    const int tid = threadIdx.x;
    const int lane = tid & 31, warp = tid >> 5;
    const int wm = (warp & 3) * 32;      // warp m offset
    const int wn = (warp >> 2) * 64;     // warp n offset

    // --- global->smem coords: 128 rows x 8 chunks(16B); thread = (row, 4 chunks)
    const int lrow = tid >> 1;
    const int lcol = (tid & 1) * 4;      // chunk base
    const __nv_bfloat16* aptr = A  + (size_t)(m0 + lrow) * lda + lcol * 8;
    const __nv_bfloat16* bptr = Bm + (size_t)(n0 + lrow) * ldb + lcol * 8;
    const uint32_t sa_st = sb + lrow * 144 + lcol * 16;
    const uint32_t sb_st = sb + ASZ + lrow * 144 + lcol * 16;

    const int NT = K / 64;               // always >= 4 here

    // prologue: stages 0,1
    #pragma unroll
    for (int s = 0; s < 2; s++) {
        const int k0 = s * 64;
        #pragma unroll
        for (int j = 0; j < 4; j++) {
            cp16(sa_st + s * STG + j * 16, aptr + k0 + j * 8);
            cp16(sb_st + s * STG + j * 16, bptr + k0 + j * 8);
        }
        CP_COMMIT();
    }

    // --- ldmatrix lane addressing
    const int lr16 = lane & 15, lc2 = lane >> 4;
    const uint32_t a_lm = sb + ((wm + lr16) * LDK + lc2 * 8) * 2;
    const uint32_t b_lm = sb + ASZ + ((wn + lr16) * LDK + lc2 * 8) * 2;

    float acc[2][8][4] = {};

    for (int kt = 0; kt < NT; kt++) {
        const int st = kt & 1;
        if (kt == NT - 1) { CP_WAIT(0); } else { CP_WAIT(1); }
        __syncthreads();

        const uint32_t a_base = a_lm + st * STG;
        const uint32_t b_base = b_lm + st * STG;
        #pragma unroll
        for (int ks = 0; ks < 4; ks++) {
            uint32_t af[2][4], bq[4][4];
            ldsm4(af[0][0], af[0][1], af[0][2], af[0][3], a_base + ks * 32);
            ldsm4(af[1][0], af[1][1], af[1][2], af[1][3], a_base + 16 * LDK * 2 + ks * 32);
            #pragma unroll
            for (int c = 0; c < 4; c++)
                ldsm4(bq[c][0], bq[c][1], bq[c][2], bq[c][3],
                      b_base + c * 16 * LDK * 2 + ks * 32);
            #pragma unroll
            for (int mt = 0; mt < 2; mt++)
                #pragma unroll
                for (int nt = 0; nt < 8; nt++) {
                    const int cch = nt >> 1, w = nt & 1;
                    mma_bf16(acc[mt][nt], af[mt][0], af[mt][1], af[mt][2], af[mt][3],
                             bq[cch][w], bq[cch][w + 2]);
                }
        }
        __syncthreads();
        if (kt + 2 < NT) {
            const int k0 = (kt + 2) * 64;
            #pragma unroll
            for (int j = 0; j < 4; j++) {
                cp16(sa_st + st * STG + j * 16, aptr + k0 + j * 8);
                cp16(sb_st + st * STG + j * 16, bptr + k0 + j * 8);
            }
            CP_COMMIT();
        }
    }

    // epilogue
    const int fr = lane >> 2;
    const int fc = (lane & 3) * 2;
    #pragma unroll
    for (int mt = 0; mt < 2; mt++) {
        #pragma unroll
        for (int nt = 0; nt < 8; nt++) {
            const int gn = n0 + wn + nt * 8 + fc;
            float b0 = 0.f, b1 = 0.f;
            if (HASBIAS) { b0 = bias[gn]; b1 = bias[gn + 1]; }
            #pragma unroll
            for (int rr = 0; rr < 2; rr++) {
                const int gm = m0 + wm + mt * 16 + fr + rr * 8;
                float v0 = acc[mt][nt][rr * 2 + 0] * alpha + b0;
                float v1 = acc[mt][nt][rr * 2 + 1] * alpha + b1;
                *(__nv_bfloat162*)&Cm[(size_t)gm * ldc + gn] = __floats2bfloat162_rn(v0, v1);
            }
        }
    }
}

// ---------------------------------------------------------------------------
// Elementwise / small kernels
// ---------------------------------------------------------------------------
__global__ void cond_linear_kernel(const float* __restrict__ cond,
                                   const float* __restrict__ w,
                                   const float* __restrict__ bias,
                                   float* __restrict__ sb) {
    __shared__ float cs[CD_];
    int b = blockIdx.y;
    for (int k = threadIdx.x; k < CD_; k += 256) cs[k] = cond[b * CD_ + k];
    __syncthreads();
    int j = blockIdx.x * 256 + threadIdx.x;
    float acc = bias[j];
    #pragma unroll 8
    for (int k = 0; k < CD_; k++) acc += cs[k] * w[k * (2 * C_) + j];
    sb[b * (2 * C_) + j] = acc;
}

__global__ void gn_stats_kernel(const float* __restrict__ x,
                                float* __restrict__ mean,
                                float* __restrict__ rinv) {
    const int bg = blockIdx.x;
    const float* p = x + (size_t)bg * CPG_ * HW_;
    float s = 0.f, ss = 0.f;
    for (int i = threadIdx.x; i < CPG_ * HW_; i += 256) {
        float v = p[i];
        s += v; ss += v * v;
    }
    __shared__ float sm_s[8], sm_ss[8];
    #pragma unroll
    for (int o = 16; o > 0; o >>= 1) {
        s  += __shfl_xor_sync(0xffffffffu, s,  o);
        ss += __shfl_xor_sync(0xffffffffu, ss, o);
    }
    if ((threadIdx.x & 31) == 0) { sm_s[threadIdx.x >> 5] = s; sm_ss[threadIdx.x >> 5] = ss; }
    __syncthreads();
    if (threadIdx.x == 0) {
        s = 0.f; ss = 0.f;
        #pragma unroll
        for (int i = 0; i < 8; i++) { s += sm_s[i]; ss += sm_ss[i]; }
        float m = s * (1.f / (CPG_ * HW_));
        float var = ss * (1.f / (CPG_ * HW_)) - m * m;
        mean[bg] = m;
        rinv[bg] = rsqrtf(var + 1e-5f);
    }
}

__global__ void gn_apply_t_kernel(const float* __restrict__ x,
                                  const float* __restrict__ sb,
                                  const float* __restrict__ mean,
                                  const float* __restrict__ rinv,
                                  __nv_bfloat16* __restrict__ t) {
    __shared__ float tile[32][33];
    const int b = blockIdx.z;
    const int c0 = blockIdx.y * 32, n0 = blockIdx.x * 32;
    #pragma unroll
    for (int i = threadIdx.y; i < 32; i += 8) {
        int c = c0 + i;
        int g = b * G_ + (c >> 3);
        float m = mean[g], r = rinv[g];
        float sc = 1.f + sb[b * 2 * C_ + c];
        float bi = sb[b * 2 * C_ + C_ + c];
        float v = x[((size_t)b * C_ + c) * HW_ + n0 + threadIdx.x];
        tile[i][threadIdx.x] = (v - m) * r * sc + bi;
    }
    __syncthreads();
    #pragma unroll
    for (int i = threadIdx.y; i < 32; i += 8) {
        int n = n0 + i;
        t[((size_t)b * HW_ + n) * C_ + c0 + threadIdx.x] =
            __float2bfloat16(tile[threadIdx.x][i]);
    }
}

__global__ void wt_kernel(const float* __restrict__ w,
                          __nv_bfloat16* __restrict__ wt, int N) {
    __shared__ float tile[32][33];
    const int k0 = blockIdx.y * 32, n0 = blockIdx.x * 32;
    #pragma unroll
    for (int i = threadIdx.y; i < 32; i += 8)
        tile[i][threadIdx.x] = w[(size_t)(k0 + i) * N + n0 + threadIdx.x];
    __syncthreads();
    #pragma unroll
    for (int i = threadIdx.y; i < 32; i += 8)
        wt[(size_t)(n0 + i) * C_ + k0 + threadIdx.x] =
            __float2bfloat16(tile[threadIdx.x][i]);
}

__global__ void vt_kernel(const __nv_bfloat16* __restrict__ qkv,
                          __nv_bfloat16* __restrict__ vt) {
    __shared__ __nv_bfloat16 tile[32][33];
    const int b = blockIdx.z;
    const int n0 = blockIdx.x * 32, c0 = blockIdx.y * 32;
    #pragma unroll
    for (int i = threadIdx.y; i < 32; i += 8)
        tile[i][threadIdx.x] =
            qkv[((size_t)b * HW_ + n0 + i) * (3 * C_) + 2 * C_ + c0 + threadIdx.x];
    __syncthreads();
    #pragma unroll
    for (int i = threadIdx.y; i < 32; i += 8)
        vt[((size_t)b * C_ + c0 + i) * HW_ + n0 + threadIdx.x] = tile[threadIdx.x][i];
}

__global__ void softmax_rows_bf16(__nv_bfloat16* __restrict__ S) {
    const size_t row = blockIdx.x;
    __nv_bfloat162* p = (__nv_bfloat162*)(S + row * (size_t)HW_);
    const int tid = threadIdx.x;
    float v[16];
    float mx = -1e30f;
    #pragma unroll
    for (int i = 0; i < 8; i++) {
        __nv_bfloat162 x2 = p[tid + i * 256];
        v[2 * i]     = __bfloat162float(x2.x);
        v[2 * i + 1] = __bfloat162float(x2.y);
        mx = fmaxf(mx, fmaxf(v[2 * i], v[2 * i + 1]));
    }
    __shared__ float sm[8];
    #pragma unroll
    for (int o = 16; o > 0; o >>= 1) mx = fmaxf(mx, __shfl_xor_sync(0xffffffffu, mx, o));
    if ((tid & 31) == 0) sm[tid >> 5] = mx;
    __syncthreads();
    mx = sm[0];
    #pragma unroll
    for (int i = 1; i < 8; i++) mx = fmaxf(mx, sm[i]);
    float s = 0.f;
    #pragma unroll
    for (int i = 0; i < 16; i++) { v[i] = __expf(v[i] - mx); s += v[i]; }
    __shared__ float sm2[8];
    #pragma unroll
    for (int o = 16; o > 0; o >>= 1) s += __shfl_xor_sync(0xffffffffu, s, o);
    if ((tid & 31) == 0) sm2[tid >> 5] = s;
    __syncthreads();
    s = 0.f;
    #pragma unroll
    for (int i = 0; i < 8; i++) s += sm2[i];
    const float inv = 1.f / s;
    #pragma unroll
    for (int i = 0; i < 8; i++)
        p[tid + i * 256] = __floats2bfloat162_rn(v[2 * i] * inv, v[2 * i + 1] * inv);
}

__global__ void residual_t_kernel(const __nv_bfloat16* __restrict__ o2,
                                  const float* __restrict__ x,
                                  float* __restrict__ out) {
    __shared__ float tile[32][33];
    const int b = blockIdx.z;
    const int n0 = blockIdx.x * 32, c0 = blockIdx.y * 32;
    #pragma unroll
    for (int i = threadIdx.y; i < 32; i += 8) {
        int n = n0 + i;
        tile[i][threadIdx.x] =
            __bfloat162float(o2[((size_t)b * HW_ + n) * C_ + c0 + threadIdx.x]);
    }
    __syncthreads();
    #pragma unroll
    for (int i = threadIdx.y; i < 32; i += 8) {
        int c = c0 + i;
        size_t idx = ((size_t)b * C_ + c) * HW_ + n0 + threadIdx.x;
        out[idx] = x[idx] + tile[threadIdx.x][i];
    }
}

// ---------------------------------------------------------------------------
// Host launcher
// ---------------------------------------------------------------------------
extern "C" void kernel_launch(void* const* d_in, const int* in_sizes, int n_in,
                              void* d_out, int out_size) {
    const float* x      = (const float*)d_in[0];
    const float* cond   = (const float*)d_in[1];
    const float* lin_w  = (const float*)d_in[2];
    const float* lin_b  = (const float*)d_in[3];
    const float* qkv_w  = (const float*)d_in[4];
    const float* qkv_b  = (const float*)d_in[5];
    const float* proj_w = (const float*)d_in[6];
    const float* proj_b = (const float*)d_in[7];
    float* out = (float*)d_out;

    float *sb, *mean, *rinv;
    __nv_bfloat16 *t, *qkv, *S, *vt, *o, *o2, *wq, *wp;
    cudaGetSymbolAddress((void**)&sb,   g_sb);
    cudaGetSymbolAddress((void**)&mean, g_mean);
    cudaGetSymbolAddress((void**)&rinv, g_rinv);
    cudaGetSymbolAddress((void**)&t,    g_t);
    cudaGetSymbolAddress((void**)&qkv,  g_qkv);
    cudaGetSymbolAddress((void**)&S,    g_S);
    cudaGetSymbolAddress((void**)&vt,   g_vt);
    cudaGetSymbolAddress((void**)&o,    g_o);
    cudaGetSymbolAddress((void**)&o2,   g_o2);
    cudaGetSymbolAddress((void**)&wq,   g_wq);
    cudaGetSymbolAddress((void**)&wp,   g_wp);

    cudaFuncSetAttribute(gemm_nt_bf16<true>,  cudaFuncAttributeMaxDynamicSharedMemorySize, GSM);
    cudaFuncSetAttribute(gemm_nt_bf16<false>, cudaFuncAttributeMaxDynamicSharedMemorySize, GSM);

    cond_linear_kernel<<<dim3(2, B_), 256>>>(cond, lin_w, lin_b, sb);
    gn_stats_kernel<<<B_ * G_, 256>>>(x, mean, rinv);
    wt_kernel<<<dim3(3 * C_ / 32, C_ / 32), dim3(32, 8)>>>(qkv_w, wq, 3 * C_);
    wt_kernel<<<dim3(C_ / 32, C_ / 32), dim3(32, 8)>>>(proj_w, wp, C_);

    gn_apply_t_kernel<<<dim3(HW_ / 32, C_ / 32, B_), dim3(32, 8)>>>(x, sb, mean, rinv, t);

    // qkv = t @ wq^T + b   [16384, 768], K=256
    gemm_nt_bf16<true><<<dim3(3 * C_ / 128, NTOK / 128, 1), 256, GSM>>>(
        t, C_, 0, wq, C_, 0, qkv, 3 * C_, 0, C_, 1.0f, qkv_b);

    // S = Q @ K^T / 16     K=256, batched
    gemm_nt_bf16<false><<<dim3(HW_ / 128, HW_ / 128, B_), 256, GSM>>>(
        qkv, 3 * C_, (size_t)HW_ * 3 * C_,
        qkv + C_, 3 * C_, (size_t)HW_ * 3 * C_,
        S, HW_, (size_t)HW_ * HW_,
        C_, 0.0625f, nullptr);

    softmax_rows_bf16<<<NTOK, 256>>>(S);

    vt_kernel<<<dim3(HW_ / 32, C_ / 32, B_), dim3(32, 8)>>>(qkv, vt);

    // O = P @ V            K=4096, batched
    gemm_nt_bf16<false><<<dim3(C_ / 128, HW_ / 128, B_), 256, GSM>>>(
        S, HW_, (size_t)HW_ * HW_,
        vt, HW_, (size_t)C_ * HW_,
        o, C_, (size_t)HW_ * C_,
        HW_, 1.0f, nullptr);

    // proj                 K=256
    gemm_nt_bf16<true><<<dim3(C_ / 128, NTOK / 128, 1), 256, GSM>>>(
        o, C_, 0, wp, C_, 0, o2, C_, 0, C_, 1.0f, proj_b);

    residual_t_kernel<<<dim3(HW_ / 32, C_ / 32, B_), dim3(32, 8)>>>(o2, x, out);
}

// round 6
// speedup vs baseline: 7.8381x; 1.2045x over previous
#include <cuda_runtime.h>
#include <cuda_bf16.h>
#include <stdint.h>
#include <math.h>

#define B_   4
#define C_   256
#define HW_  4096
#define G_   32
#define CPG_ 8
#define CD_  512
#define NTOK (B_*HW_)

// ---------------------------------------------------------------------------
// Scratch (device globals)
// ---------------------------------------------------------------------------
__device__ float g_sb[B_ * 2 * C_];
__device__ float g_mean[B_ * G_];
__device__ float g_rinv[B_ * G_];
__device__ __nv_bfloat16 g_t[NTOK * C_];
__device__ __nv_bfloat16 g_qkv[NTOK * 3 * C_];
__device__ __nv_bfloat16 g_o[NTOK * C_];
__device__ __nv_bfloat16 g_o2[NTOK * C_];
__device__ __nv_bfloat16 g_wq[3 * C_ * C_];
__device__ __nv_bfloat16 g_wp[C_ * C_];

// ---------------------------------------------------------------------------
// PTX helpers
// ---------------------------------------------------------------------------
__device__ __forceinline__ uint32_t smem_u32(const void* p) {
    uint32_t a;
    asm("{ .reg .u64 t; cvta.to.shared.u64 t, %1; cvt.u32.u64 %0, t; }" : "=r"(a) : "l"(p));
    return a;
}
__device__ __forceinline__ void cp16(uint32_t dst, const void* src) {
    asm volatile("cp.async.cg.shared.global [%0], [%1], 16;" :: "r"(dst), "l"(src));
}
#define CP_COMMIT() asm volatile("cp.async.commit_group;" ::: "memory")
#define CP_WAIT(n)  asm volatile("cp.async.wait_group %0;" :: "n"(n) : "memory")

__device__ __forceinline__ void ldsm4(uint32_t& r0, uint32_t& r1, uint32_t& r2, uint32_t& r3,
                                      uint32_t addr) {
    asm volatile("ldmatrix.sync.aligned.m8n8.x4.shared.b16 {%0,%1,%2,%3}, [%4];"
                 : "=r"(r0), "=r"(r1), "=r"(r2), "=r"(r3) : "r"(addr));
}
__device__ __forceinline__ void ldsm4t(uint32_t& r0, uint32_t& r1, uint32_t& r2, uint32_t& r3,
                                       uint32_t addr) {
    asm volatile("ldmatrix.sync.aligned.m8n8.x4.trans.shared.b16 {%0,%1,%2,%3}, [%4];"
                 : "=r"(r0), "=r"(r1), "=r"(r2), "=r"(r3) : "r"(addr));
}
__device__ __forceinline__ void mma_bf16(float c[4],
                                         uint32_t a0, uint32_t a1, uint32_t a2, uint32_t a3,
                                         uint32_t b0, uint32_t b1) {
    asm volatile(
        "mma.sync.aligned.m16n8k16.row.col.f32.bf16.bf16.f32 "
        "{%0,%1,%2,%3},{%4,%5,%6,%7},{%8,%9},{%0,%1,%2,%3};\n"
        : "+f"(c[0]), "+f"(c[1]), "+f"(c[2]), "+f"(c[3])
        : "r"(a0), "r"(a1), "r"(a2), "r"(a3), "r"(b0), "r"(b1));
}
__device__ __forceinline__ uint32_t packbf(float a, float b) {
    __nv_bfloat162 h = __floats2bfloat162_rn(a, b);
    return *(uint32_t*)&h;
}

// ---------------------------------------------------------------------------
// Fused flash attention: O = softmax(Q K^T / 16) V
//   qkv layout [B, HW, 768] (Q | K | V).  Per CTA: 128 Q rows; 64 iters of
//   64-key blocks.  8 warps x 16 rows.  Online softmax, O in registers.
// ---------------------------------------------------------------------------
#define FLDK 264                                  // halves per smem row
#define FQ_BYTES (128 * FLDK * 2)                 // 67584
#define FK_BYTES (64 * FLDK * 2)                  // 33792
#define FK_OFF(s) (FQ_BYTES + (s) * FK_BYTES)
#define FV_OFF(s) (FQ_BYTES + 2 * FK_BYTES + (s) * FK_BYTES)
#define FSM_TOT  (FQ_BYTES + 4 * FK_BYTES)        // 202752

__global__ void __launch_bounds__(256, 1)
flash_attn(const __nv_bfloat16* __restrict__ qkv, __nv_bfloat16* __restrict__ O) {
    extern __shared__ char smraw[];
    const uint32_t sb = smem_u32(smraw);
    const int b = blockIdx.y;
    const int m0 = blockIdx.x * 128;
    const int tid = threadIdx.x;
    const int lane = tid & 31, warp = tid >> 5;
    const __nv_bfloat16* base = qkv + (size_t)b * HW_ * 768;

    // ---- prologue loads ----
    // Q: 128 rows x 32 chunks(16B); thread -> (row = tid/2, 16 chunks)
    {
        const int qr = tid >> 1, qc = (tid & 1) * 16;
        const __nv_bfloat16* src = base + (size_t)(m0 + qr) * 768 + qc * 8;
        const uint32_t dst = sb + (qr * FLDK + qc * 8) * 2;
        #pragma unroll
        for (int i = 0; i < 16; i++) cp16(dst + i * 16, src + i * 8);
    }
    // K/V block loader: 64 rows x 32 chunks each; thread -> (row = tid/4, 8 chunks)
    const int kr = tid >> 2, kc = (tid & 3) * 8;
    auto load_kv = [&](int st, int j) {
        const __nv_bfloat16* srck = base + (size_t)(j * 64 + kr) * 768 + 256 + kc * 8;
        const __nv_bfloat16* srcv = srck + 256;
        const uint32_t dk = sb + FK_OFF(st) + (kr * FLDK + kc * 8) * 2;
        const uint32_t dv = sb + FV_OFF(st) + (kr * FLDK + kc * 8) * 2;
        #pragma unroll
        for (int i = 0; i < 8; i++) { cp16(dk + i * 16, srck + i * 8); }
        #pragma unroll
        for (int i = 0; i < 8; i++) { cp16(dv + i * 16, srcv + i * 8); }
    };
    load_kv(0, 0);
    CP_COMMIT();            // group 0 = Q + KV0
    load_kv(1, 1);
    CP_COMMIT();            // group 1 = KV1

    // ---- ldmatrix lane addressing ----
    const int lr16 = lane & 15, lc2 = lane >> 4;
    const uint32_t q_lm = sb + ((warp * 16 + lr16) * FLDK + lc2 * 8) * 2;

    float o_[32][4];
    #pragma unroll
    for (int i = 0; i < 32; i++)
        #pragma unroll
        for (int j = 0; j < 4; j++) o_[i][j] = 0.f;
    float m0r = -1e30f, m1r = -1e30f, l0r = 0.f, l1r = 0.f;

    for (int j = 0; j < 64; j++) {
        if (j == 63) { CP_WAIT(0); } else { CP_WAIT(1); }
        __syncthreads();
        const int st = j & 1;
        const uint32_t k_lm = sb + FK_OFF(st) + (lr16 * FLDK + lc2 * 8) * 2;
        const uint32_t v_lm = sb + FV_OFF(st) + (lr16 * FLDK + lc2 * 8) * 2;

        // ---- S = Q K^T ----
        float s_[8][4];
        #pragma unroll
        for (int i = 0; i < 8; i++)
            #pragma unroll
            for (int c = 0; c < 4; c++) s_[i][c] = 0.f;
        #pragma unroll
        for (int ks = 0; ks < 16; ks++) {
            uint32_t a0, a1, a2, a3;
            ldsm4(a0, a1, a2, a3, q_lm + ks * 32);
            #pragma unroll
            for (int np = 0; np < 4; np++) {
                uint32_t r0, r1, r2, r3;
                ldsm4(r0, r1, r2, r3, k_lm + np * 16 * FLDK * 2 + ks * 32);
                mma_bf16(s_[2 * np],     a0, a1, a2, a3, r0, r2);
                mma_bf16(s_[2 * np + 1], a0, a1, a2, a3, r1, r3);
            }
        }

        // ---- online softmax (scale 1/16) ----
        float bm0 = -1e30f, bm1 = -1e30f;
        #pragma unroll
        for (int i = 0; i < 8; i++) {
            #pragma unroll
            for (int c = 0; c < 4; c++) s_[i][c] *= 0.0625f;
            bm0 = fmaxf(bm0, fmaxf(s_[i][0], s_[i][1]));
            bm1 = fmaxf(bm1, fmaxf(s_[i][2], s_[i][3]));
        }
        bm0 = fmaxf(bm0, __shfl_xor_sync(0xffffffffu, bm0, 1));
        bm0 = fmaxf(bm0, __shfl_xor_sync(0xffffffffu, bm0, 2));
        bm1 = fmaxf(bm1, __shfl_xor_sync(0xffffffffu, bm1, 1));
        bm1 = fmaxf(bm1, __shfl_xor_sync(0xffffffffu, bm1, 2));
        const float mn0 = fmaxf(m0r, bm0), mn1 = fmaxf(m1r, bm1);
        const float sc0 = __expf(m0r - mn0), sc1 = __expf(m1r - mn1);
        m0r = mn0; m1r = mn1;

        uint32_t pb[8][2];
        float ls0 = 0.f, ls1 = 0.f;
        #pragma unroll
        for (int i = 0; i < 8; i++) {
            float p00 = __expf(s_[i][0] - mn0);
            float p01 = __expf(s_[i][1] - mn0);
            float p10 = __expf(s_[i][2] - mn1);
            float p11 = __expf(s_[i][3] - mn1);
            ls0 += p00 + p01; ls1 += p10 + p11;
            pb[i][0] = packbf(p00, p01);
            pb[i][1] = packbf(p10, p11);
        }
        l0r = l0r * sc0 + ls0;
        l1r = l1r * sc1 + ls1;
        #pragma unroll
        for (int i = 0; i < 32; i++) {
            o_[i][0] *= sc0; o_[i][1] *= sc0;
            o_[i][2] *= sc1; o_[i][3] *= sc1;
        }

        // ---- O += P V ----
        #pragma unroll
        for (int kk = 0; kk < 4; kk++) {
            const uint32_t a0 = pb[2 * kk][0], a1 = pb[2 * kk][1];
            const uint32_t a2 = pb[2 * kk + 1][0], a3 = pb[2 * kk + 1][1];
            #pragma unroll
            for (int np = 0; np < 16; np++) {
                uint32_t r0, r1, r2, r3;
                ldsm4t(r0, r1, r2, r3, v_lm + kk * 16 * FLDK * 2 + np * 32);
                mma_bf16(o_[2 * np],     a0, a1, a2, a3, r0, r1);
                mma_bf16(o_[2 * np + 1], a0, a1, a2, a3, r2, r3);
            }
        }
        __syncthreads();
        if (j + 2 < 64) { load_kv(st, j + 2); CP_COMMIT(); }
    }

    // ---- epilogue ----
    l0r += __shfl_xor_sync(0xffffffffu, l0r, 1);
    l0r += __shfl_xor_sync(0xffffffffu, l0r, 2);
    l1r += __shfl_xor_sync(0xffffffffu, l1r, 1);
    l1r += __shfl_xor_sync(0xffffffffu, l1r, 2);
    const float inv0 = 1.f / l0r, inv1 = 1.f / l1r;
    const int row0 = m0 + warp * 16 + (lane >> 2);
    const int colb = (lane & 3) * 2;
    __nv_bfloat16* op0 = O + ((size_t)b * HW_ + row0) * C_;
    __nv_bfloat16* op1 = op0 + 8 * C_;
    #pragma unroll
    for (int nt = 0; nt < 32; nt++) {
        const int col = nt * 8 + colb;
        *(__nv_bfloat162*)&op0[col] = __floats2bfloat162_rn(o_[nt][0] * inv0, o_[nt][1] * inv0);
        *(__nv_bfloat162*)&op1[col] = __floats2bfloat162_rn(o_[nt][2] * inv1, o_[nt][3] * inv1);
    }
}

// ---------------------------------------------------------------------------
// bf16 NT GEMM (qkv / proj): C = A[M,K] @ B[N,K]^T + bias
// ---------------------------------------------------------------------------
#define LDK 72
#define ASZ (128 * LDK * 2)
#define STG (2 * ASZ)
#define GSM (2 * STG)

template <bool HASBIAS>
__global__ void __launch_bounds__(256)
gemm_nt_bf16(const __nv_bfloat16* __restrict__ A, int lda, size_t sA,
             const __nv_bfloat16* __restrict__ Bm, int ldb, size_t sB,
             __nv_bfloat16* __restrict__ Cm, int ldc, size_t sC,
             int K, float alpha, const float* __restrict__ bias) {
    extern __shared__ char smraw[];
    const uint32_t sb = smem_u32(smraw);
    const int bz = blockIdx.z;
    A  += (size_t)bz * sA;
    Bm += (size_t)bz * sB;
    Cm += (size_t)bz * sC;
    const int m0 = blockIdx.y * 128, n0 = blockIdx.x * 128;
    const int tid = threadIdx.x;
    const int lane = tid & 31, warp = tid >> 5;
    const int wm = (warp & 3) * 32, wn = (warp >> 2) * 64;

    const int lrow = tid >> 1, lcol = (tid & 1) * 4;
    const __nv_bfloat16* aptr = A  + (size_t)(m0 + lrow) * lda + lcol * 8;
    const __nv_bfloat16* bptr = Bm + (size_t)(n0 + lrow) * ldb + lcol * 8;
    const uint32_t sa_st = sb + lrow * 144 + lcol * 16;
    const uint32_t sb_st = sb + ASZ + lrow * 144 + lcol * 16;
    const int NT = K / 64;

    #pragma unroll
    for (int s = 0; s < 2; s++) {
        const int k0 = s * 64;
        #pragma unroll
        for (int j = 0; j < 4; j++) {
            cp16(sa_st + s * STG + j * 16, aptr + k0 + j * 8);
            cp16(sb_st + s * STG + j * 16, bptr + k0 + j * 8);
        }
        CP_COMMIT();
    }

    const int lr16 = lane & 15, lc2 = lane >> 4;
    const uint32_t a_lm = sb + ((wm + lr16) * LDK + lc2 * 8) * 2;
    const uint32_t b_lm = sb + ASZ + ((wn + lr16) * LDK + lc2 * 8) * 2;

    float acc[2][8][4] = {};
    for (int kt = 0; kt < NT; kt++) {
        const int st = kt & 1;
        if (kt == NT - 1) { CP_WAIT(0); } else { CP_WAIT(1); }
        __syncthreads();
        const uint32_t a_base = a_lm + st * STG;
        const uint32_t b_base = b_lm + st * STG;
        #pragma unroll
        for (int ks = 0; ks < 4; ks++) {
            uint32_t af[2][4], bq[4][4];
            ldsm4(af[0][0], af[0][1], af[0][2], af[0][3], a_base + ks * 32);
            ldsm4(af[1][0], af[1][1], af[1][2], af[1][3], a_base + 16 * LDK * 2 + ks * 32);
            #pragma unroll
            for (int c = 0; c < 4; c++)
                ldsm4(bq[c][0], bq[c][1], bq[c][2], bq[c][3],
                      b_base + c * 16 * LDK * 2 + ks * 32);
            #pragma unroll
            for (int mt = 0; mt < 2; mt++)
                #pragma unroll
                for (int nt = 0; nt < 8; nt++) {
                    const int cch = nt >> 1, w = nt & 1;
                    mma_bf16(acc[mt][nt], af[mt][0], af[mt][1], af[mt][2], af[mt][3],
                             bq[cch][w], bq[cch][w + 2]);
                }
        }
        __syncthreads();
        if (kt + 2 < NT) {
            const int k0 = (kt + 2) * 64;
            #pragma unroll
            for (int j = 0; j < 4; j++) {
                cp16(sa_st + st * STG + j * 16, aptr + k0 + j * 8);
                cp16(sb_st + st * STG + j * 16, bptr + k0 + j * 8);
            }
            CP_COMMIT();
        }
    }

    const int fr = lane >> 2, fc = (lane & 3) * 2;
    #pragma unroll
    for (int mt = 0; mt < 2; mt++)
        #pragma unroll
        for (int nt = 0; nt < 8; nt++) {
            const int gn = n0 + wn + nt * 8 + fc;
            float b0 = 0.f, b1 = 0.f;
            if (HASBIAS) { b0 = bias[gn]; b1 = bias[gn + 1]; }
            #pragma unroll
            for (int rr = 0; rr < 2; rr++) {
                const int gm = m0 + wm + mt * 16 + fr + rr * 8;
                float v0 = acc[mt][nt][rr * 2 + 0] * alpha + b0;
                float v1 = acc[mt][nt][rr * 2 + 1] * alpha + b1;
                *(__nv_bfloat162*)&Cm[(size_t)gm * ldc + gn] = __floats2bfloat162_rn(v0, v1);
            }
        }
}

// ---------------------------------------------------------------------------
// Elementwise / small kernels
// ---------------------------------------------------------------------------
__global__ void cond_linear_kernel(const float* __restrict__ cond,
                                   const float* __restrict__ w,
                                   const float* __restrict__ bias,
                                   float* __restrict__ sb) {
    __shared__ float cs[CD_];
    int b = blockIdx.y;
    for (int k = threadIdx.x; k < CD_; k += 256) cs[k] = cond[b * CD_ + k];
    __syncthreads();
    int j = blockIdx.x * 256 + threadIdx.x;
    float acc = bias[j];
    #pragma unroll 8
    for (int k = 0; k < CD_; k++) acc += cs[k] * w[k * (2 * C_) + j];
    sb[b * (2 * C_) + j] = acc;
}

__global__ void gn_stats_kernel(const float* __restrict__ x,
                                float* __restrict__ mean,
                                float* __restrict__ rinv) {
    const int bg = blockIdx.x;
    const float* p = x + (size_t)bg * CPG_ * HW_;
    float s = 0.f, ss = 0.f;
    for (int i = threadIdx.x; i < CPG_ * HW_; i += 256) {
        float v = p[i];
        s += v; ss += v * v;
    }
    __shared__ float sm_s[8], sm_ss[8];
    #pragma unroll
    for (int o = 16; o > 0; o >>= 1) {
        s  += __shfl_xor_sync(0xffffffffu, s,  o);
        ss += __shfl_xor_sync(0xffffffffu, ss, o);
    }
    if ((threadIdx.x & 31) == 0) { sm_s[threadIdx.x >> 5] = s; sm_ss[threadIdx.x >> 5] = ss; }
    __syncthreads();
    if (threadIdx.x == 0) {
        s = 0.f; ss = 0.f;
        #pragma unroll
        for (int i = 0; i < 8; i++) { s += sm_s[i]; ss += sm_ss[i]; }
        float m = s * (1.f / (CPG_ * HW_));
        float var = ss * (1.f / (CPG_ * HW_)) - m * m;
        mean[bg] = m;
        rinv[bg] = rsqrtf(var + 1e-5f);
    }
}

__global__ void gn_apply_t_kernel(const float* __restrict__ x,
                                  const float* __restrict__ sb,
                                  const float* __restrict__ mean,
                                  const float* __restrict__ rinv,
                                  __nv_bfloat16* __restrict__ t) {
    __shared__ float tile[32][33];
    const int b = blockIdx.z;
    const int c0 = blockIdx.y * 32, n0 = blockIdx.x * 32;
    #pragma unroll
    for (int i = threadIdx.y; i < 32; i += 8) {
        int c = c0 + i;
        int g = b * G_ + (c >> 3);
        float m = mean[g], r = rinv[g];
        float sc = 1.f + sb[b * 2 * C_ + c];
        float bi = sb[b * 2 * C_ + C_ + c];
        float v = x[((size_t)b * C_ + c) * HW_ + n0 + threadIdx.x];
        tile[i][threadIdx.x] = (v - m) * r * sc + bi;
    }
    __syncthreads();
    #pragma unroll
    for (int i = threadIdx.y; i < 32; i += 8) {
        int n = n0 + i;
        t[((size_t)b * HW_ + n) * C_ + c0 + threadIdx.x] =
            __float2bfloat16(tile[threadIdx.x][i]);
    }
}

__global__ void wt_kernel(const float* __restrict__ w,
                          __nv_bfloat16* __restrict__ wt, int N) {
    __shared__ float tile[32][33];
    const int k0 = blockIdx.y * 32, n0 = blockIdx.x * 32;
    #pragma unroll
    for (int i = threadIdx.y; i < 32; i += 8)
        tile[i][threadIdx.x] = w[(size_t)(k0 + i) * N + n0 + threadIdx.x];
    __syncthreads();
    #pragma unroll
    for (int i = threadIdx.y; i < 32; i += 8)
        wt[(size_t)(n0 + i) * C_ + k0 + threadIdx.x] =
            __float2bfloat16(tile[threadIdx.x][i]);
}

__global__ void residual_t_kernel(const __nv_bfloat16* __restrict__ o2,
                                  const float* __restrict__ x,
                                  float* __restrict__ out) {
    __shared__ float tile[32][33];
    const int b = blockIdx.z;
    const int n0 = blockIdx.x * 32, c0 = blockIdx.y * 32;
    #pragma unroll
    for (int i = threadIdx.y; i < 32; i += 8) {
        int n = n0 + i;
        tile[i][threadIdx.x] =
            __bfloat162float(o2[((size_t)b * HW_ + n) * C_ + c0 + threadIdx.x]);
    }
    __syncthreads();
    #pragma unroll
    for (int i = threadIdx.y; i < 32; i += 8) {
        int c = c0 + i;
        size_t idx = ((size_t)b * C_ + c) * HW_ + n0 + threadIdx.x;
        out[idx] = x[idx] + tile[threadIdx.x][i];
    }
}

// ---------------------------------------------------------------------------
// Host launcher
// ---------------------------------------------------------------------------
extern "C" void kernel_launch(void* const* d_in, const int* in_sizes, int n_in,
                              void* d_out, int out_size) {
    const float* x      = (const float*)d_in[0];
    const float* cond   = (const float*)d_in[1];
    const float* lin_w  = (const float*)d_in[2];
    const float* lin_b  = (const float*)d_in[3];
    const float* qkv_w  = (const float*)d_in[4];
    const float* qkv_b  = (const float*)d_in[5];
    const float* proj_w = (const float*)d_in[6];
    const float* proj_b = (const float*)d_in[7];
    float* out = (float*)d_out;

    float *sb, *mean, *rinv;
    __nv_bfloat16 *t, *qkv, *o, *o2, *wq, *wp;
    cudaGetSymbolAddress((void**)&sb,   g_sb);
    cudaGetSymbolAddress((void**)&mean, g_mean);
    cudaGetSymbolAddress((void**)&rinv, g_rinv);
    cudaGetSymbolAddress((void**)&t,    g_t);
    cudaGetSymbolAddress((void**)&qkv,  g_qkv);
    cudaGetSymbolAddress((void**)&o,    g_o);
    cudaGetSymbolAddress((void**)&o2,   g_o2);
    cudaGetSymbolAddress((void**)&wq,   g_wq);
    cudaGetSymbolAddress((void**)&wp,   g_wp);

    cudaFuncSetAttribute(gemm_nt_bf16<true>,  cudaFuncAttributeMaxDynamicSharedMemorySize, GSM);
    cudaFuncSetAttribute(gemm_nt_bf16<false>, cudaFuncAttributeMaxDynamicSharedMemorySize, GSM);
    cudaFuncSetAttribute(flash_attn, cudaFuncAttributeMaxDynamicSharedMemorySize, FSM_TOT);

    cond_linear_kernel<<<dim3(2, B_), 256>>>(cond, lin_w, lin_b, sb);
    gn_stats_kernel<<<B_ * G_, 256>>>(x, mean, rinv);
    wt_kernel<<<dim3(3 * C_ / 32, C_ / 32), dim3(32, 8)>>>(qkv_w, wq, 3 * C_);
    wt_kernel<<<dim3(C_ / 32, C_ / 32), dim3(32, 8)>>>(proj_w, wp, C_);

    gn_apply_t_kernel<<<dim3(HW_ / 32, C_ / 32, B_), dim3(32, 8)>>>(x, sb, mean, rinv, t);

    // qkv = t @ wq^T + b   [16384, 768], K=256
    gemm_nt_bf16<true><<<dim3(3 * C_ / 128, NTOK / 128, 1), 256, GSM>>>(
        t, C_, 0, wq, C_, 0, qkv, 3 * C_, 0, C_, 1.0f, qkv_b);

    // fused attention -> o [B, HW, C]
    flash_attn<<<dim3(HW_ / 128, B_), 256, FSM_TOT>>>(qkv, o);

    // proj              K=256
    gemm_nt_bf16<true><<<dim3(C_ / 128, NTOK / 128, 1), 256, GSM>>>(
        o, C_, 0, wp, C_, 0, o2, C_, 0, C_, 1.0f, proj_b);

    residual_t_kernel<<<dim3(HW_ / 32, C_ / 32, B_), dim3(32, 8)>>>(o2, x, out);
}

// round 7
// speedup vs baseline: 7.8392x; 1.0001x over previous
#include <cuda_runtime.h>
#include <cuda_bf16.h>
#include <stdint.h>
#include <math.h>

#define B_   4
#define C_   256
#define HW_  4096
#define G_   32
#define CPG_ 8
#define CD_  512
#define NTOK (B_*HW_)

// scale folded into Q columns of qkv output: (1/16) * log2(e)
#define QSCALE_F 0.0901650905f

// ---------------------------------------------------------------------------
// Scratch (device globals)
// ---------------------------------------------------------------------------
__device__ float g_sb[B_ * 2 * C_];
__device__ float g_mean[B_ * G_];
__device__ float g_rinv[B_ * G_];
__device__ __nv_bfloat16 g_t[NTOK * C_];
__device__ __nv_bfloat16 g_qkv[NTOK * 3 * C_];
__device__ __nv_bfloat16 g_o[NTOK * C_];
__device__ __nv_bfloat16 g_o2[NTOK * C_];
__device__ __nv_bfloat16 g_wq[3 * C_ * C_];
__device__ __nv_bfloat16 g_wp[C_ * C_];

// ---------------------------------------------------------------------------
// PTX helpers
// ---------------------------------------------------------------------------
__device__ __forceinline__ uint32_t smem_u32(const void* p) {
    uint32_t a;
    asm("{ .reg .u64 t; cvta.to.shared.u64 t, %1; cvt.u32.u64 %0, t; }" : "=r"(a) : "l"(p));
    return a;
}
__device__ __forceinline__ void cp16(uint32_t dst, const void* src) {
    asm volatile("cp.async.cg.shared.global [%0], [%1], 16;" :: "r"(dst), "l"(src));
}
#define CP_COMMIT() asm volatile("cp.async.commit_group;" ::: "memory")
#define CP_WAIT(n)  asm volatile("cp.async.wait_group %0;" :: "n"(n) : "memory")

__device__ __forceinline__ void ldsm4(uint32_t& r0, uint32_t& r1, uint32_t& r2, uint32_t& r3,
                                      uint32_t addr) {
    asm volatile("ldmatrix.sync.aligned.m8n8.x4.shared.b16 {%0,%1,%2,%3}, [%4];"
                 : "=r"(r0), "=r"(r1), "=r"(r2), "=r"(r3) : "r"(addr));
}
__device__ __forceinline__ void ldsm4t(uint32_t& r0, uint32_t& r1, uint32_t& r2, uint32_t& r3,
                                       uint32_t addr) {
    asm volatile("ldmatrix.sync.aligned.m8n8.x4.trans.shared.b16 {%0,%1,%2,%3}, [%4];"
                 : "=r"(r0), "=r"(r1), "=r"(r2), "=r"(r3) : "r"(addr));
}
__device__ __forceinline__ void mma_bf16(float c[4],
                                         uint32_t a0, uint32_t a1, uint32_t a2, uint32_t a3,
                                         uint32_t b0, uint32_t b1) {
    asm volatile(
        "mma.sync.aligned.m16n8k16.row.col.f32.bf16.bf16.f32 "
        "{%0,%1,%2,%3},{%4,%5,%6,%7},{%8,%9},{%0,%1,%2,%3};\n"
        : "+f"(c[0]), "+f"(c[1]), "+f"(c[2]), "+f"(c[3])
        : "r"(a0), "r"(a1), "r"(a2), "r"(a3), "r"(b0), "r"(b1));
}
__device__ __forceinline__ uint32_t packbf(float a, float b) {
    __nv_bfloat162 h = __floats2bfloat162_rn(a, b);
    return *(uint32_t*)&h;
}

// ---------------------------------------------------------------------------
// Fused flash attention: O = softmax2(Q' K^T) V   (Q' pre-scaled by QSCALE_F)
// ---------------------------------------------------------------------------
#define FLDK 264
#define FQ_BYTES (128 * FLDK * 2)
#define FK_BYTES (64 * FLDK * 2)
#define FK_OFF(s) (FQ_BYTES + (s) * FK_BYTES)
#define FV_OFF(s) (FQ_BYTES + 2 * FK_BYTES + (s) * FK_BYTES)
#define FSM_TOT  (FQ_BYTES + 4 * FK_BYTES)

__global__ void __launch_bounds__(256, 1)
flash_attn(const __nv_bfloat16* __restrict__ qkv, __nv_bfloat16* __restrict__ O) {
    extern __shared__ char smraw[];
    const uint32_t sb = smem_u32(smraw);
    const int b = blockIdx.y;
    const int m0 = blockIdx.x * 128;
    const int tid = threadIdx.x;
    const int lane = tid & 31, warp = tid >> 5;
    const __nv_bfloat16* base = qkv + (size_t)b * HW_ * 768;

    {   // Q prologue
        const int qr = tid >> 1, qc = (tid & 1) * 16;
        const __nv_bfloat16* src = base + (size_t)(m0 + qr) * 768 + qc * 8;
        const uint32_t dst = sb + (qr * FLDK + qc * 8) * 2;
        #pragma unroll
        for (int i = 0; i < 16; i++) cp16(dst + i * 16, src + i * 8);
    }
    const int kr = tid >> 2, kc = (tid & 3) * 8;
    auto load_kv = [&](int st, int j) {
        const __nv_bfloat16* srck = base + (size_t)(j * 64 + kr) * 768 + 256 + kc * 8;
        const __nv_bfloat16* srcv = srck + 256;
        const uint32_t dk = sb + FK_OFF(st) + (kr * FLDK + kc * 8) * 2;
        const uint32_t dv = sb + FV_OFF(st) + (kr * FLDK + kc * 8) * 2;
        #pragma unroll
        for (int i = 0; i < 8; i++) { cp16(dk + i * 16, srck + i * 8); }
        #pragma unroll
        for (int i = 0; i < 8; i++) { cp16(dv + i * 16, srcv + i * 8); }
    };
    load_kv(0, 0);
    CP_COMMIT();
    load_kv(1, 1);
    CP_COMMIT();

    const int lr16 = lane & 15, lc2 = lane >> 4;
    const uint32_t q_lm = sb + ((warp * 16 + lr16) * FLDK + lc2 * 8) * 2;

    float o_[32][4];
    #pragma unroll
    for (int i = 0; i < 32; i++)
        #pragma unroll
        for (int j = 0; j < 4; j++) o_[i][j] = 0.f;
    float m0r = -1e30f, m1r = -1e30f, l0r = 0.f, l1r = 0.f;

    for (int j = 0; j < 64; j++) {
        if (j == 63) { CP_WAIT(0); } else { CP_WAIT(1); }
        __syncthreads();
        const int st = j & 1;
        const uint32_t k_lm = sb + FK_OFF(st) + (lr16 * FLDK + lc2 * 8) * 2;
        const uint32_t v_lm = sb + FV_OFF(st) + (lr16 * FLDK + lc2 * 8) * 2;

        // ---- S = Q' K^T (already log2-scaled) ----
        float s_[8][4];
        #pragma unroll
        for (int i = 0; i < 8; i++)
            #pragma unroll
            for (int c = 0; c < 4; c++) s_[i][c] = 0.f;
        #pragma unroll
        for (int ks = 0; ks < 16; ks++) {
            uint32_t a0, a1, a2, a3;
            ldsm4(a0, a1, a2, a3, q_lm + ks * 32);
            #pragma unroll
            for (int np = 0; np < 4; np++) {
                uint32_t r0, r1, r2, r3;
                ldsm4(r0, r1, r2, r3, k_lm + np * 16 * FLDK * 2 + ks * 32);
                mma_bf16(s_[2 * np],     a0, a1, a2, a3, r0, r2);
                mma_bf16(s_[2 * np + 1], a0, a1, a2, a3, r1, r3);
            }
        }

        // ---- online softmax (base 2) ----
        float bm0 = -1e30f, bm1 = -1e30f;
        #pragma unroll
        for (int i = 0; i < 8; i++) {
            bm0 = fmaxf(bm0, fmaxf(s_[i][0], s_[i][1]));
            bm1 = fmaxf(bm1, fmaxf(s_[i][2], s_[i][3]));
        }
        bm0 = fmaxf(bm0, __shfl_xor_sync(0xffffffffu, bm0, 1));
        bm0 = fmaxf(bm0, __shfl_xor_sync(0xffffffffu, bm0, 2));
        bm1 = fmaxf(bm1, __shfl_xor_sync(0xffffffffu, bm1, 1));
        bm1 = fmaxf(bm1, __shfl_xor_sync(0xffffffffu, bm1, 2));
        const float pm0 = m0r, pm1 = m1r;
        const float mn0 = fmaxf(pm0, bm0), mn1 = fmaxf(pm1, bm1);
        m0r = mn0; m1r = mn1;

        if (mn0 != pm0 || mn1 != pm1) {     // rescale only when max moved
            const float sc0 = exp2f(pm0 - mn0), sc1 = exp2f(pm1 - mn1);
            l0r *= sc0; l1r *= sc1;
            #pragma unroll
            for (int i = 0; i < 32; i++) {
                o_[i][0] *= sc0; o_[i][1] *= sc0;
                o_[i][2] *= sc1; o_[i][3] *= sc1;
            }
        }

        uint32_t pb[8][2];
        float ls0 = 0.f, ls1 = 0.f;
        #pragma unroll
        for (int i = 0; i < 8; i++) {
            float p00 = exp2f(s_[i][0] - mn0);
            float p01 = exp2f(s_[i][1] - mn0);
            float p10 = exp2f(s_[i][2] - mn1);
            float p11 = exp2f(s_[i][3] - mn1);
            ls0 += p00 + p01; ls1 += p10 + p11;
            pb[i][0] = packbf(p00, p01);
            pb[i][1] = packbf(p10, p11);
        }
        l0r += ls0;
        l1r += ls1;

        // ---- O += P V ----
        #pragma unroll
        for (int kk = 0; kk < 4; kk++) {
            const uint32_t a0 = pb[2 * kk][0], a1 = pb[2 * kk][1];
            const uint32_t a2 = pb[2 * kk + 1][0], a3 = pb[2 * kk + 1][1];
            #pragma unroll
            for (int np = 0; np < 16; np++) {
                uint32_t r0, r1, r2, r3;
                ldsm4t(r0, r1, r2, r3, v_lm + kk * 16 * FLDK * 2 + np * 32);
                mma_bf16(o_[2 * np],     a0, a1, a2, a3, r0, r1);
                mma_bf16(o_[2 * np + 1], a0, a1, a2, a3, r2, r3);
            }
        }
        __syncthreads();
        if (j + 2 < 64) { load_kv(st, j + 2); CP_COMMIT(); }
    }

    // ---- epilogue ----
    l0r += __shfl_xor_sync(0xffffffffu, l0r, 1);
    l0r += __shfl_xor_sync(0xffffffffu, l0r, 2);
    l1r += __shfl_xor_sync(0xffffffffu, l1r, 1);
    l1r += __shfl_xor_sync(0xffffffffu, l1r, 2);
    const float inv0 = 1.f / l0r, inv1 = 1.f / l1r;
    const int row0 = m0 + warp * 16 + (lane >> 2);
    const int colb = (lane & 3) * 2;
    __nv_bfloat16* op0 = O + ((size_t)b * HW_ + row0) * C_;
    __nv_bfloat16* op1 = op0 + 8 * C_;
    #pragma unroll
    for (int nt = 0; nt < 32; nt++) {
        const int col = nt * 8 + colb;
        *(__nv_bfloat162*)&op0[col] = __floats2bfloat162_rn(o_[nt][0] * inv0, o_[nt][1] * inv0);
        *(__nv_bfloat162*)&op1[col] = __floats2bfloat162_rn(o_[nt][2] * inv1, o_[nt][3] * inv1);
    }
}

// ---------------------------------------------------------------------------
// bf16 NT GEMM: C = A[M,K] @ B[N,K]^T + bias; QSCALE scales cols<256 by QSCALE_F
// ---------------------------------------------------------------------------
#define LDK 72
#define ASZ (128 * LDK * 2)
#define STG (2 * ASZ)
#define GSM (2 * STG)

template <bool HASBIAS, bool QSC>
__global__ void __launch_bounds__(256)
gemm_nt_bf16(const __nv_bfloat16* __restrict__ A, int lda, size_t sA,
             const __nv_bfloat16* __restrict__ Bm, int ldb, size_t sB,
             __nv_bfloat16* __restrict__ Cm, int ldc, size_t sC,
             int K, const float* __restrict__ bias) {
    extern __shared__ char smraw[];
    const uint32_t sb = smem_u32(smraw);
    const int bz = blockIdx.z;
    A  += (size_t)bz * sA;
    Bm += (size_t)bz * sB;
    Cm += (size_t)bz * sC;
    const int m0 = blockIdx.y * 128, n0 = blockIdx.x * 128;
    const int tid = threadIdx.x;
    const int lane = tid & 31, warp = tid >> 5;
    const int wm = (warp & 3) * 32, wn = (warp >> 2) * 64;

    const int lrow = tid >> 1, lcol = (tid & 1) * 4;
    const __nv_bfloat16* aptr = A  + (size_t)(m0 + lrow) * lda + lcol * 8;
    const __nv_bfloat16* bptr = Bm + (size_t)(n0 + lrow) * ldb + lcol * 8;
    const uint32_t sa_st = sb + lrow * 144 + lcol * 16;
    const uint32_t sb_st = sb + ASZ + lrow * 144 + lcol * 16;
    const int NT = K / 64;

    #pragma unroll
    for (int s = 0; s < 2; s++) {
        const int k0 = s * 64;
        #pragma unroll
        for (int j = 0; j < 4; j++) {
            cp16(sa_st + s * STG + j * 16, aptr + k0 + j * 8);
            cp16(sb_st + s * STG + j * 16, bptr + k0 + j * 8);
        }
        CP_COMMIT();
    }

    const int lr16 = lane & 15, lc2 = lane >> 4;
    const uint32_t a_lm = sb + ((wm + lr16) * LDK + lc2 * 8) * 2;
    const uint32_t b_lm = sb + ASZ + ((wn + lr16) * LDK + lc2 * 8) * 2;

    float acc[2][8][4] = {};
    for (int kt = 0; kt < NT; kt++) {
        const int st = kt & 1;
        if (kt == NT - 1) { CP_WAIT(0); } else { CP_WAIT(1); }
        __syncthreads();
        const uint32_t a_base = a_lm + st * STG;
        const uint32_t b_base = b_lm + st * STG;
        #pragma unroll
        for (int ks = 0; ks < 4; ks++) {
            uint32_t af[2][4], bq[4][4];
            ldsm4(af[0][0], af[0][1], af[0][2], af[0][3], a_base + ks * 32);
            ldsm4(af[1][0], af[1][1], af[1][2], af[1][3], a_base + 16 * LDK * 2 + ks * 32);
            #pragma unroll
            for (int c = 0; c < 4; c++)
                ldsm4(bq[c][0], bq[c][1], bq[c][2], bq[c][3],
                      b_base + c * 16 * LDK * 2 + ks * 32);
            #pragma unroll
            for (int mt = 0; mt < 2; mt++)
                #pragma unroll
                for (int nt = 0; nt < 8; nt++) {
                    const int cch = nt >> 1, w = nt & 1;
                    mma_bf16(acc[mt][nt], af[mt][0], af[mt][1], af[mt][2], af[mt][3],
                             bq[cch][w], bq[cch][w + 2]);
                }
        }
        __syncthreads();
        if (kt + 2 < NT) {
            const int k0 = (kt + 2) * 64;
            #pragma unroll
            for (int j = 0; j < 4; j++) {
                cp16(sa_st + st * STG + j * 16, aptr + k0 + j * 8);
                cp16(sb_st + st * STG + j * 16, bptr + k0 + j * 8);
            }
            CP_COMMIT();
        }
    }

    const int fr = lane >> 2, fc = (lane & 3) * 2;
    #pragma unroll
    for (int mt = 0; mt < 2; mt++)
        #pragma unroll
        for (int nt = 0; nt < 8; nt++) {
            const int gn = n0 + wn + nt * 8 + fc;
            float b0 = 0.f, b1 = 0.f;
            if (HASBIAS) { b0 = bias[gn]; b1 = bias[gn + 1]; }
            float cs = 1.f;
            if (QSC) cs = (gn < C_) ? QSCALE_F : 1.f;
            #pragma unroll
            for (int rr = 0; rr < 2; rr++) {
                const int gm = m0 + wm + mt * 16 + fr + rr * 8;
                float v0 = (acc[mt][nt][rr * 2 + 0] + b0) * cs;
                float v1 = (acc[mt][nt][rr * 2 + 1] + b1) * cs;
                *(__nv_bfloat162*)&Cm[(size_t)gm * ldc + gn] = __floats2bfloat162_rn(v0, v1);
            }
        }
}

// ---------------------------------------------------------------------------
// Elementwise / small kernels
// ---------------------------------------------------------------------------
__global__ void cond_linear_kernel(const float* __restrict__ cond,
                                   const float* __restrict__ w,
                                   const float* __restrict__ bias,
                                   float* __restrict__ sb) {
    __shared__ float cs[CD_];
    int b = blockIdx.y;
    for (int k = threadIdx.x; k < CD_; k += 256) cs[k] = cond[b * CD_ + k];
    __syncthreads();
    int j = blockIdx.x * 256 + threadIdx.x;
    float acc = bias[j];
    #pragma unroll 8
    for (int k = 0; k < CD_; k++) acc += cs[k] * w[k * (2 * C_) + j];
    sb[b * (2 * C_) + j] = acc;
}

__global__ void gn_stats_kernel(const float* __restrict__ x,
                                float* __restrict__ mean,
                                float* __restrict__ rinv) {
    const int bg = blockIdx.x;
    const float* p = x + (size_t)bg * CPG_ * HW_;
    float s = 0.f, ss = 0.f;
    for (int i = threadIdx.x; i < CPG_ * HW_; i += 256) {
        float v = p[i];
        s += v; ss += v * v;
    }
    __shared__ float sm_s[8], sm_ss[8];
    #pragma unroll
    for (int o = 16; o > 0; o >>= 1) {
        s  += __shfl_xor_sync(0xffffffffu, s,  o);
        ss += __shfl_xor_sync(0xffffffffu, ss, o);
    }
    if ((threadIdx.x & 31) == 0) { sm_s[threadIdx.x >> 5] = s; sm_ss[threadIdx.x >> 5] = ss; }
    __syncthreads();
    if (threadIdx.x == 0) {
        s = 0.f; ss = 0.f;
        #pragma unroll
        for (int i = 0; i < 8; i++) { s += sm_s[i]; ss += sm_ss[i]; }
        float m = s * (1.f / (CPG_ * HW_));
        float var = ss * (1.f / (CPG_ * HW_)) - m * m;
        mean[bg] = m;
        rinv[bg] = rsqrtf(var + 1e-5f);
    }
}

__global__ void gn_apply_t_kernel(const float* __restrict__ x,
                                  const float* __restrict__ sb,
                                  const float* __restrict__ mean,
                                  const float* __restrict__ rinv,
                                  __nv_bfloat16* __restrict__ t) {
    __shared__ float tile[32][33];
    const int b = blockIdx.z;
    const int c0 = blockIdx.y * 32, n0 = blockIdx.x * 32;
    #pragma unroll
    for (int i = threadIdx.y; i < 32; i += 8) {
        int c = c0 + i;
        int g = b * G_ + (c >> 3);
        float m = mean[g], r = rinv[g];
        float sc = 1.f + sb[b * 2 * C_ + c];
        float bi = sb[b * 2 * C_ + C_ + c];
        float v = x[((size_t)b * C_ + c) * HW_ + n0 + threadIdx.x];
        tile[i][threadIdx.x] = (v - m) * r * sc + bi;
    }
    __syncthreads();
    #pragma unroll
    for (int i = threadIdx.y; i < 32; i += 8) {
        int n = n0 + i;
        t[((size_t)b * HW_ + n) * C_ + c0 + threadIdx.x] =
            __float2bfloat16(tile[threadIdx.x][i]);
    }
}

__global__ void wt_kernel(const float* __restrict__ w,
                          __nv_bfloat16* __restrict__ wt, int N) {
    __shared__ float tile[32][33];
    const int k0 = blockIdx.y * 32, n0 = blockIdx.x * 32;
    #pragma unroll
    for (int i = threadIdx.y; i < 32; i += 8)
        tile[i][threadIdx.x] = w[(size_t)(k0 + i) * N + n0 + threadIdx.x];
    __syncthreads();
    #pragma unroll
    for (int i = threadIdx.y; i < 32; i += 8)
        wt[(size_t)(n0 + i) * C_ + k0 + threadIdx.x] =
            __float2bfloat16(tile[threadIdx.x][i]);
}

__global__ void residual_t_kernel(const __nv_bfloat16* __restrict__ o2,
                                  const float* __restrict__ x,
                                  float* __restrict__ out) {
    __shared__ float tile[32][33];
    const int b = blockIdx.z;
    const int n0 = blockIdx.x * 32, c0 = blockIdx.y * 32;
    #pragma unroll
    for (int i = threadIdx.y; i < 32; i += 8) {
        int n = n0 + i;
        tile[i][threadIdx.x] =
            __bfloat162float(o2[((size_t)b * HW_ + n) * C_ + c0 + threadIdx.x]);
    }
    __syncthreads();
    #pragma unroll
    for (int i = threadIdx.y; i < 32; i += 8) {
        int c = c0 + i;
        size_t idx = ((size_t)b * C_ + c) * HW_ + n0 + threadIdx.x;
        out[idx] = x[idx] + tile[threadIdx.x][i];
    }
}

// ---------------------------------------------------------------------------
// Host launcher  (flash_attn is the 6th launch -> ncu -s 5 -c 1 captures it)
// ---------------------------------------------------------------------------
extern "C" void kernel_launch(void* const* d_in, const int* in_sizes, int n_in,
                              void* d_out, int out_size) {
    const float* x      = (const float*)d_in[0];
    const float* cond   = (const float*)d_in[1];
    const float* lin_w  = (const float*)d_in[2];
    const float* lin_b  = (const float*)d_in[3];
    const float* qkv_w  = (const float*)d_in[4];
    const float* qkv_b  = (const float*)d_in[5];
    const float* proj_w = (const float*)d_in[6];
    const float* proj_b = (const float*)d_in[7];
    float* out = (float*)d_out;

    float *sb, *mean, *rinv;
    __nv_bfloat16 *t, *qkv, *o, *o2, *wq, *wp;
    cudaGetSymbolAddress((void**)&sb,   g_sb);
    cudaGetSymbolAddress((void**)&mean, g_mean);
    cudaGetSymbolAddress((void**)&rinv, g_rinv);
    cudaGetSymbolAddress((void**)&t,    g_t);
    cudaGetSymbolAddress((void**)&qkv,  g_qkv);
    cudaGetSymbolAddress((void**)&o,    g_o);
    cudaGetSymbolAddress((void**)&o2,   g_o2);
    cudaGetSymbolAddress((void**)&wq,   g_wq);
    cudaGetSymbolAddress((void**)&wp,   g_wp);

    cudaFuncSetAttribute((const void*)gemm_nt_bf16<true, true>,
                         cudaFuncAttributeMaxDynamicSharedMemorySize, GSM);
    cudaFuncSetAttribute((const void*)gemm_nt_bf16<true, false>,
                         cudaFuncAttributeMaxDynamicSharedMemorySize, GSM);
    cudaFuncSetAttribute((const void*)flash_attn,
                         cudaFuncAttributeMaxDynamicSharedMemorySize, FSM_TOT);

    // 1..5
    cond_linear_kernel<<<dim3(2, B_), 256>>>(cond, lin_w, lin_b, sb);
    gn_stats_kernel<<<B_ * G_, 256>>>(x, mean, rinv);
    wt_kernel<<<dim3(3 * C_ / 32, C_ / 32), dim3(32, 8)>>>(qkv_w, wq, 3 * C_);
    gn_apply_t_kernel<<<dim3(HW_ / 32, C_ / 32, B_), dim3(32, 8)>>>(x, sb, mean, rinv, t);
    gemm_nt_bf16<true, true><<<dim3(3 * C_ / 128, NTOK / 128, 1), 256, GSM>>>(
        t, C_, 0, wq, C_, 0, qkv, 3 * C_, 0, C_, qkv_b);

    // 6: fused attention (profiled)
    flash_attn<<<dim3(HW_ / 128, B_), 256, FSM_TOT>>>(qkv, o);

    // 7..9
    wt_kernel<<<dim3(C_ / 32, C_ / 32), dim3(32, 8)>>>(proj_w, wp, C_);
    gemm_nt_bf16<true, false><<<dim3(C_ / 128, NTOK / 128, 1), 256, GSM>>>(
        o, C_, 0, wp, C_, 0, o2, C_, 0, C_, proj_b);
    residual_t_kernel<<<dim3(HW_ / 32, C_ / 32, B_), dim3(32, 8)>>>(o2, x, out);
}